// round 9
// baseline (speedup 1.0000x reference)
#include <cuda_runtime.h>
#include <cuda_bf16.h>
#include <cstdint>

#define NN 50000
#define NE 800000
#define D  128

static __device__ __forceinline__ float rrelu_f(float x) {
    const float SLOPE = (1.0f/8.0f + 1.0f/3.0f) * 0.5f;
    return x >= 0.0f ? x : x * SLOPE;
}

// ---------------- scratch layout (floats) ----------------
#define ND        (NN * D)                 // 6,400,000
#define OFF_XA    0                        // Xagg 50k x 128
#define OFF_EA    (ND)                     // Eagg 50k x 128 (atomic target)
#define OFF_PE    (2 * ND)                 // 50k x 256: [E0 | E1] = EA@[Wn0e|Wn1e]
#define OFF_NX    (4 * ND)                 // XA@Wn0u
#define OFF_S0    (5 * ND)                 // x@Wl0
#define OFF_PX    (6 * ND)                 // 50k x 256: [h1@Wl1 | h1@Wo_top + bo]
#define OFF_N1    (8 * ND)                 // H1@Wn1u
#define OFF_H1    (9 * ND)                 // gather of h1
#define OFF_HCAT  (10 * ND)                // 50k x 256
#define OFF_B2    (12 * ND)                // composite bias [0|bo], 256 floats
#define OFF_INT   (12 * ND + 256)
#define NI_HIST 0
#define NI_INCL 50176
#define NI_BLK  100352
#define NI_BOFF 100416
#define NI_RP   100480
#define NI_WP   150912
#define NI_PS   201088
#define NI_TOTAL 1001088
#define SCRATCH_N (OFF_INT + NI_TOTAL)

__device__ float g_scratch[SCRATCH_N];

// bf16 weight images: 8 chunks x 64KB ([n][k] bf16 hi then lo).
// 0:Wl0 1:Wn0e 2:Wn1e 3:Wn0u 4:Wl1 5:Wo_top 6:Wn1u 7:Wo_bot
__device__ __align__(16) unsigned char g_bimg[8 * 65536];

// ---------------- PTX helpers ----------------
__device__ __forceinline__ uint32_t smem_u32(const void* p) {
    uint32_t a;
    asm("{ .reg .u64 t; cvta.to.shared.u64 t, %1; cvt.u32.u64 %0, t; }" : "=r"(a) : "l"(p));
    return a;
}

__device__ __forceinline__ void ldsm_x4(uint32_t addr, uint32_t* r) {
    asm volatile("ldmatrix.sync.aligned.m8n8.x4.shared.b16 {%0,%1,%2,%3}, [%4];"
                 : "=r"(r[0]), "=r"(r[1]), "=r"(r[2]), "=r"(r[3]) : "r"(addr));
}

__device__ __forceinline__ void mma_bf16(float* c, const uint32_t* a,
                                         uint32_t b0, uint32_t b1) {
    asm volatile("mma.sync.aligned.m16n8k16.row.col.f32.bf16.bf16.f32 "
                 "{%0,%1,%2,%3}, {%4,%5,%6,%7}, {%8,%9}, {%0,%1,%2,%3};"
                 : "+f"(c[0]), "+f"(c[1]), "+f"(c[2]), "+f"(c[3])
                 : "r"(a[0]), "r"(a[1]), "r"(a[2]), "r"(a[3]), "r"(b0), "r"(b1));
}

__device__ __forceinline__ void red_add_v4(float* p, float4 v) {
    asm volatile("red.global.add.v4.f32 [%0], {%1,%2,%3,%4};"
                 :: "l"(p), "f"(v.x), "f"(v.y), "f"(v.z), "f"(v.w)
                 : "memory");
}

// ---------------- small kernels ----------------
__global__ void zero_f4(float4* p, int n4) {
    int i = blockIdx.x * blockDim.x + threadIdx.x;
    if (i < n4) p[i] = make_float4(0.f, 0.f, 0.f, 0.f);
}

__global__ void zero_hist(int* hist) {
    int i = blockIdx.x * blockDim.x + threadIdx.x;
    if (i < NN) hist[i] = 0;
}

__global__ void hist_k(const int* __restrict__ dst, int* __restrict__ hist) {
    int i = blockIdx.x * blockDim.x + threadIdx.x;
    if (i < NE) atomicAdd(hist + __ldg(dst + i), 1);
}

__global__ void scanA(const int* __restrict__ hist, int* __restrict__ incl,
                      int* __restrict__ blk) {
    __shared__ int s[1024];
    int t = threadIdx.x;
    int i = blockIdx.x * 1024 + t;
    int v = (i < NN) ? hist[i] : 0;
    s[t] = v;
    __syncthreads();
#pragma unroll
    for (int off = 1; off < 1024; off <<= 1) {
        int add = (t >= off) ? s[t - off] : 0;
        __syncthreads();
        s[t] += add;
        __syncthreads();
    }
    incl[i] = s[t];
    if (t == 1023) blk[blockIdx.x] = s[t];
}

__global__ void scanB(const int* __restrict__ blk, int* __restrict__ boff) {
    __shared__ int s[64];
    int t = threadIdx.x;
    if (t < 49) s[t] = blk[t];
    __syncthreads();
    if (t == 0) {
        int run = 0;
        for (int b = 0; b < 49; b++) { int v = s[b]; s[b] = run; run += v; }
    }
    __syncthreads();
    if (t < 49) boff[t] = s[t];
}

__global__ void scanC(const int* __restrict__ incl, const int* __restrict__ boff,
                      const int* __restrict__ hist,
                      int* __restrict__ rp, int* __restrict__ wp) {
    int t = threadIdx.x;
    int i = blockIdx.x * 1024 + t;
    if (i < NN) {
        int inc = incl[i] + boff[blockIdx.x];
        rp[i + 1] = inc;
        wp[i] = inc - hist[i];
    }
    if (i == 0) rp[0] = 0;
}

__global__ void permute_k(const int* __restrict__ src, const int* __restrict__ dst,
                          int* __restrict__ wp, int* __restrict__ ps) {
    int i = blockIdx.x * blockDim.x + threadIdx.x;
    if (i >= NE) return;
    int d = __ldg(dst + i);
    int pos = atomicAdd(wp + d, 1);
    ps[pos] = __ldg(src + i);
}

// ---------------- EA: atomic RED scatter (no CSR needed) ----------------
__global__ void scatter_e(const float* __restrict__ e,
                          const int* __restrict__ dst,
                          float* __restrict__ EA) {
    int w    = (blockIdx.x * blockDim.x + threadIdx.x) >> 5;
    int lane = threadIdx.x & 31;
    if (w >= NE) return;
    int d = __ldg(dst + w);
    float4 v = *reinterpret_cast<const float4*>(e + (size_t)w * D + lane * 4);
    red_add_v4(EA + (size_t)d * D + lane * 4, v);
}

// ---------------- CSR gather: O[n] = sum T[src], T ld ldT, O ld 128 ----------
__global__ void gather_T(const float* __restrict__ T, int ldT,
                         const int* __restrict__ rp,
                         const int* __restrict__ ps,
                         float* __restrict__ O) {
    int w    = (blockIdx.x * blockDim.x + threadIdx.x) >> 5;
    int lane = threadIdx.x & 31;
    if (w >= NN) return;
    int beg = __ldg(rp + w), end = __ldg(rp + w + 1);
    float4 acc = make_float4(0.f, 0.f, 0.f, 0.f);
    for (int j = beg; j < end; j += 32) {
        int m = min(32, end - j);
        int sidx = (lane < m) ? __ldg(ps + j + lane) : 0;
        for (int t = 0; t < m; t++) {
            int s = __shfl_sync(0xffffffffu, sidx, t);
            float4 v = *reinterpret_cast<const float4*>(T + (size_t)s * ldT + lane * 4);
            acc.x += v.x; acc.y += v.y; acc.z += v.z; acc.w += v.w;
        }
    }
    *reinterpret_cast<float4*>(O + (size_t)w * D + lane * 4) = acc;
}

// ---------------- elementwise layer epilogue ----------------
// hc[n,c] = rrelu( (Nn + En)/max(cnt,1) + (cnt>0)*bn + Sn + bl )
__global__ void epi_k(const float* __restrict__ Nn,   // ld 128
                      const float* __restrict__ En,   // ld 256
                      const float* __restrict__ Sn, int ldS,
                      const int* __restrict__ rp,
                      const float* __restrict__ bn,
                      const float* __restrict__ bl,
                      float* __restrict__ hc) {       // ld 256
    int idx = blockIdx.x * blockDim.x + threadIdx.x;  // over ND/4
    if (idx >= ND / 4) return;
    int node = idx >> 5;
    int c4   = (idx & 31) * 4;
    int cn = __ldg(rp + node + 1) - __ldg(rp + node);
    float inv = 1.0f / fmaxf((float)cn, 1.0f);
    float g = (cn > 0) ? 1.0f : 0.0f;
    float4 a = *reinterpret_cast<const float4*>(Nn + (size_t)node * 128 + c4);
    float4 b = *reinterpret_cast<const float4*>(En + (size_t)node * 256 + c4);
    float4 s = *reinterpret_cast<const float4*>(Sn + (size_t)node * ldS + c4);
    float4 b4 = *reinterpret_cast<const float4*>(bn + c4);
    float4 l4 = *reinterpret_cast<const float4*>(bl + c4);
    float4 o;
    o.x = rrelu_f((a.x + b.x) * inv + g * b4.x + s.x + l4.x);
    o.y = rrelu_f((a.y + b.y) * inv + g * b4.y + s.y + l4.y);
    o.z = rrelu_f((a.z + b.z) * inv + g * b4.z + s.z + l4.z);
    o.w = rrelu_f((a.w + b.w) * inv + g * b4.w + s.w + l4.w);
    *reinterpret_cast<float4*>(hc + (size_t)node * 256 + c4) = o;
}

// ---------------- weight image prep (+ composite bias fill) ----------------
__global__ void prep_B(const float* __restrict__ Wn0, const float* __restrict__ Wl0,
                       const float* __restrict__ Wn1, const float* __restrict__ Wl1,
                       const float* __restrict__ Wo, const float* __restrict__ bo,
                       unsigned char* __restrict__ img, float* __restrict__ bias2) {
    int ci = blockIdx.x;
    int t = threadIdx.x;  // 128
    if (ci == 8) {
        bias2[t] = 0.f;
        bias2[128 + t] = bo[t];
        return;
    }
    const float* W;
    switch (ci) {
        case 0: W = Wl0; break;
        case 1: W = Wn0 + 128 * 128; break;   // Wn0e
        case 2: W = Wn1 + 128 * 128; break;   // Wn1e
        case 3: W = Wn0; break;               // Wn0u
        case 4: W = Wl1; break;
        case 5: W = Wo; break;                // Wo_top
        case 6: W = Wn1; break;               // Wn1u
        default: W = Wo + 128 * 128; break;   // Wo_bot
    }
    unsigned char* hi_img = img + ci * 65536;
    unsigned char* lo_img = hi_img + 32768;

    __shared__ float sw[64][129];
    for (int kt = 0; kt < 2; kt++) {
        for (int i = t; i < 64 * 128; i += 128)
            sw[i >> 7][i & 127] = W[kt * 64 * 128 + i];
        __syncthreads();
        int n = t;
#pragma unroll
        for (int u = 0; u < 8; u++) {
            union { __nv_bfloat16 h[8]; uint4 v; } hi;
            union { __nv_bfloat16 h[8]; uint4 v; } lo;
#pragma unroll
            for (int j = 0; j < 8; j++) {
                float f = sw[u * 8 + j][n];
                __nv_bfloat16 hb = __float2bfloat16(f);
                hi.h[j] = hb;
                lo.h[j] = __float2bfloat16(f - __bfloat162float(hb));
            }
            uint32_t off = (uint32_t)(n * 256 + kt * 128 + u * 16);
            *reinterpret_cast<uint4*>(hi_img + off) = hi.v;
            *reinterpret_cast<uint4*>(lo_img + off) = lo.v;
        }
        __syncthreads();
    }
}

// ---------------- HMMA bf16x3 GEMM: 128 x (128*NCH) tile, K=128, 512 thr ----
// C = A @ chunks (+bias) (+Cin if Cin != nullptr)
#define SA_HI 0
#define SA_LO 34816
#define SB_BASE 69632
#define CHUNK_SM 69632
#define SM_SZ(NCH) (SB_BASE + (NCH) * CHUNK_SM)

template<int NCH>
__global__ __launch_bounds__(512, 1)
void gemm_mma(const float* __restrict__ A, int lda,
              const unsigned char* __restrict__ Bimg,
              float* __restrict__ C, int ldc,
              const float* __restrict__ bias,
              const float* __restrict__ Cin, int ldcin, int M) {
    constexpr int MI = 2 * NCH;
    constexpr int NW = 4 * NCH;
    extern __shared__ unsigned char smem[];
    uint32_t sb = smem_u32(smem);
    int tid  = threadIdx.x;
    int lane = tid & 31;
    int wid  = tid >> 5;
    int wn   = wid % NW;
    int wm   = wid / NW;
    int bm   = blockIdx.y * 128;

    float acc[MI][4][4];
#pragma unroll
    for (int mi = 0; mi < MI; mi++)
#pragma unroll
        for (int ni = 0; ni < 4; ni++)
#pragma unroll
            for (int q = 0; q < 4; q++) acc[mi][ni][q] = 0.f;

    {
        int r = tid >> 2;
        int q = tid & 3;
        bool valid = (bm + r) < M;
        const float4* ap = reinterpret_cast<const float4*>(
            A + (size_t)(bm + r) * lda + q * 32);
        float4 z4 = make_float4(0.f, 0.f, 0.f, 0.f);
#pragma unroll
        for (int u = 0; u < 4; u++) {
            float4 f0 = valid ? ap[u * 2]     : z4;
            float4 f1 = valid ? ap[u * 2 + 1] : z4;
            float fs[8] = {f0.x, f0.y, f0.z, f0.w, f1.x, f1.y, f1.z, f1.w};
            union { __nv_bfloat16 b[8]; uint4 v; } hi;
            union { __nv_bfloat16 b[8]; uint4 v; } lo;
#pragma unroll
            for (int j = 0; j < 8; j++) {
                __nv_bfloat16 hb = __float2bfloat16(fs[j]);
                hi.b[j] = hb;
                lo.b[j] = __float2bfloat16(fs[j] - __bfloat162float(hb));
            }
            uint32_t off = (uint32_t)(r * 272 + q * 64 + u * 16);
            *reinterpret_cast<uint4*>(smem + SA_HI + off) = hi.v;
            *reinterpret_cast<uint4*>(smem + SA_LO + off) = lo.v;
        }
    }
#pragma unroll
    for (int c = 0; c < NCH; c++) {
        const unsigned char* ch = Bimg + (size_t)(blockIdx.x * NCH + c) * 65536;
        unsigned char* db = smem + SB_BASE + c * CHUNK_SM;
#pragma unroll
        for (int i = 0; i < 4; i++) {
            int linear = tid + i * 512;
            int row = linear >> 4;
            int c16 = linear & 15;
            uint32_t soff = (uint32_t)(row * 256 + c16 * 16);
            uint32_t doff = (uint32_t)(row * 272 + c16 * 16);
            *reinterpret_cast<uint4*>(db + doff) =
                *reinterpret_cast<const uint4*>(ch + soff);
            *reinterpret_cast<uint4*>(db + 34816 + doff) =
                *reinterpret_cast<const uint4*>(ch + 32768 + soff);
        }
    }
    __syncthreads();

    uint32_t a_row = (uint32_t)(wm * (32 * NCH) + (lane & 15));
    uint32_t a_cb  = (uint32_t)((lane >> 4) * 16);
    uint32_t sbB   = sb + SB_BASE + (wn >> 2) * CHUNK_SM;
    uint32_t b_n   = (uint32_t)((wn & 3) * 32 + ((lane >> 4) << 3) + (lane & 7));
    uint32_t b_cb  = (uint32_t)(((lane >> 3) & 1) * 16);
#pragma unroll
    for (int ks = 0; ks < 8; ks++) {
        uint32_t kb = (uint32_t)(ks * 32);
        uint32_t Ahi[MI][4], Alo[MI][4];
#pragma unroll
        for (int mi = 0; mi < MI; mi++) {
            ldsm_x4(sb + SA_HI + (a_row + mi * 16) * 272 + kb + a_cb, Ahi[mi]);
            ldsm_x4(sb + SA_LO + (a_row + mi * 16) * 272 + kb + a_cb, Alo[mi]);
        }
#pragma unroll
        for (int nj = 0; nj < 2; nj++) {
            uint32_t bh[4], bl[4];
            uint32_t baddr = (b_n + nj * 16) * 272 + kb + b_cb;
            ldsm_x4(sbB + baddr, bh);
            ldsm_x4(sbB + 34816 + baddr, bl);
#pragma unroll
            for (int mi = 0; mi < MI; mi++) {
                mma_bf16(acc[mi][2 * nj],     Ahi[mi], bh[0], bh[1]);
                mma_bf16(acc[mi][2 * nj],     Ahi[mi], bl[0], bl[1]);
                mma_bf16(acc[mi][2 * nj],     Alo[mi], bh[0], bh[1]);
                mma_bf16(acc[mi][2 * nj + 1], Ahi[mi], bh[2], bh[3]);
                mma_bf16(acc[mi][2 * nj + 1], Ahi[mi], bl[2], bl[3]);
                mma_bf16(acc[mi][2 * nj + 1], Alo[mi], bh[2], bh[3]);
            }
        }
    }

    int lrow = lane >> 2;
    int lcol = (lane & 3) * 2;
#pragma unroll
    for (int mi = 0; mi < MI; mi++) {
        int row0 = bm + wm * (32 * NCH) + mi * 16 + lrow;
#pragma unroll
        for (int ni = 0; ni < 4; ni++) {
            int gcol = blockIdx.x * (128 * NCH) + wn * 32 + ni * 8 + lcol;
            float b0 = 0.f, b1 = 0.f;
            if (bias) {
                b0 = __ldg(bias + gcol);
                b1 = __ldg(bias + gcol + 1);
            }
            if (row0 < M) {
                float* cp = C + (size_t)row0 * ldc + gcol;
                float2 v = make_float2(acc[mi][ni][0] + b0, acc[mi][ni][1] + b1);
                if (Cin) {
                    const float* ip = Cin + (size_t)row0 * ldcin + gcol;
                    v.x += ip[0]; v.y += ip[1];
                }
                *reinterpret_cast<float2*>(cp) = v;
            }
            if (row0 + 8 < M) {
                float* cp = C + (size_t)(row0 + 8) * ldc + gcol;
                float2 v = make_float2(acc[mi][ni][2] + b0, acc[mi][ni][3] + b1);
                if (Cin) {
                    const float* ip = Cin + (size_t)(row0 + 8) * ldcin + gcol;
                    v.x += ip[0]; v.y += ip[1];
                }
                *reinterpret_cast<float2*>(cp) = v;
            }
        }
    }
}

// ---------------- launch ----------------
extern "C" void kernel_launch(void* const* d_in, const int* in_sizes, int n_in,
                              void* d_out, int out_size) {
    const float* x   = (const float*)d_in[0];
    const float* e   = (const float*)d_in[1];
    const int*   src = (const int*)d_in[2];
    const int*   dst = (const int*)d_in[3];
    const float* Wn0 = (const float*)d_in[4];
    const float* bn0 = (const float*)d_in[5];
    const float* Wl0 = (const float*)d_in[6];
    const float* bl0 = (const float*)d_in[7];
    const float* Wn1 = (const float*)d_in[8];
    const float* bn1 = (const float*)d_in[9];
    const float* Wl1 = (const float*)d_in[10];
    const float* bl1 = (const float*)d_in[11];
    const float* Wo  = (const float*)d_in[12];
    const float* bo  = (const float*)d_in[13];
    float* out = (float*)d_out;

    float* S = nullptr;
    cudaGetSymbolAddress((void**)&S, g_scratch);
    unsigned char* BI = nullptr;
    cudaGetSymbolAddress((void**)&BI, g_bimg);

    float* XA   = S + OFF_XA;
    float* EA   = S + OFF_EA;
    float* PE   = S + OFF_PE;
    float* NX   = S + OFF_NX;
    float* S0   = S + OFF_S0;
    float* PX   = S + OFF_PX;
    float* N1   = S + OFF_N1;
    float* H1   = S + OFF_H1;
    float* HCAT = S + OFF_HCAT;
    float* B2   = S + OFF_B2;
    int*   I    = (int*)(S + OFF_INT);
    int* hist = I + NI_HIST;
    int* incl = I + NI_INCL;
    int* blk  = I + NI_BLK;
    int* boff = I + NI_BOFF;
    int* rp   = I + NI_RP;
    int* wp   = I + NI_WP;
    int* ps   = I + NI_PS;

    static cudaStream_t s1 = nullptr, s2 = nullptr;
    static cudaEvent_t evRoot, evEA, evXA, evE0, evN1;
    if (!s1) {
        cudaStreamCreateWithFlags(&s1, cudaStreamNonBlocking);
        cudaStreamCreateWithFlags(&s2, cudaStreamNonBlocking);
        cudaEventCreateWithFlags(&evRoot, cudaEventDisableTiming);
        cudaEventCreateWithFlags(&evEA,   cudaEventDisableTiming);
        cudaEventCreateWithFlags(&evXA,   cudaEventDisableTiming);
        cudaEventCreateWithFlags(&evE0,   cudaEventDisableTiming);
        cudaEventCreateWithFlags(&evN1,   cudaEventDisableTiming);
    }

    cudaFuncSetAttribute(gemm_mma<2>,
                         cudaFuncAttributeMaxDynamicSharedMemorySize, SM_SZ(2));
    cudaFuncSetAttribute(gemm_mma<1>,
                         cudaFuncAttributeMaxDynamicSharedMemorySize, SM_SZ(1));

    const int MT = (NN + 127) / 128;
    const dim3 GT(1, MT);
    const int GW = (NN * 32 + 255) / 256;
    const int EPB = (ND / 4 + 255) / 256;
    const int SCT = (NE * 32 + 255) / 256;

    // fork root
    cudaEventRecord(evRoot, 0);
    cudaStreamWaitEvent(s1, evRoot, 0);
    cudaStreamWaitEvent(s2, evRoot, 0);

    // s1: EA via atomic RED (no CSR dependency, starts immediately)
    zero_f4<<<(ND / 4 + 255) / 256, 256, 0, s1>>>((float4*)EA, ND / 4);
    scatter_e<<<SCT, 256, 0, s1>>>(e, dst, EA);
    cudaEventRecord(evEA, s1);

    // s2: CSR build + XA gather (L2-bound, overlaps s1's DRAM scatter)
    zero_hist<<<(NN + 255) / 256, 256, 0, s2>>>(hist);
    hist_k<<<(NE + 255) / 256, 256, 0, s2>>>(dst, hist);
    scanA<<<49, 1024, 0, s2>>>(hist, incl, blk);
    scanB<<<1, 64, 0, s2>>>(blk, boff);
    scanC<<<49, 1024, 0, s2>>>(incl, boff, hist, rp, wp);
    permute_k<<<(NE + 255) / 256, 256, 0, s2>>>(src, dst, wp, ps);
    gather_T<<<GW, 256, 0, s2>>>(x, D, rp, ps, XA);
    cudaEventRecord(evXA, s2);

    // s0: weight images (+bias2), S0 = x @ Wl0
    prep_B<<<9, 128>>>(Wn0, Wl0, Wn1, Wl1, Wo, bo, BI, B2);
    gemm_mma<1><<<GT, 512, SM_SZ(1)>>>(x, D, BI + 0 * 65536, S0, 128, nullptr, nullptr, 0, NN);

    // s0: NX = XA @ Wn0u
    cudaStreamWaitEvent(0, evXA, 0);
    gemm_mma<1><<<GT, 512, SM_SZ(1)>>>(XA, D, BI + 3 * 65536, NX, 128, nullptr, nullptr, 0, NN);

    // s0: PE = EA @ [Wn0e | Wn1e]
    cudaStreamWaitEvent(0, evEA, 0);
    gemm_mma<2><<<GT, 512, SM_SZ(2)>>>(EA, D, BI + 1 * 65536, PE, 256, nullptr, nullptr, 0, NN);

    // s0: epi0 -> h1 (HCAT cols 0-127)
    epi_k<<<EPB, 256>>>(NX, PE, S0, 128, rp, bn0, bl0, HCAT);
    cudaEventRecord(evE0, 0);

    // s1: gather_h1 -> H1; N1 = H1 @ Wn1u  (overlaps s0's PX)
    cudaStreamWaitEvent(s1, evE0, 0);
    gather_T<<<GW, 256, 0, s1>>>(HCAT, 256, rp, ps, H1);
    gemm_mma<1><<<GT, 512, SM_SZ(1), s1>>>(H1, D, BI + 6 * 65536, N1, 128, nullptr, nullptr, 0, NN);
    cudaEventRecord(evN1, s1);

    // s0: PX = h1 @ [Wl1 | Wo_top] + [0|bo]   (wide, shares A-load)
    gemm_mma<2><<<GT, 512, SM_SZ(2)>>>(HCAT, 256, BI + 4 * 65536, PX, 256, B2, nullptr, 0, NN);

    // s0: epi1 -> h2 (HCAT cols 128-255); Sn = PX left half (ld 256)
    cudaStreamWaitEvent(0, evN1, 0);
    epi_k<<<EPB, 256>>>(N1, PE + 128, PX, 256, rp, bn1, bl1, HCAT + 128);

    // s0: out = h2 @ Wo_bot + PX_right
    gemm_mma<1><<<GT, 512, SM_SZ(1)>>>(HCAT + 128, 256, BI + 7 * 65536, out, 128,
                                       nullptr, PX + 128, 256, NN);
}

// round 10
// speedup vs baseline: 1.4358x; 1.4358x over previous
#include <cuda_runtime.h>
#include <cuda_bf16.h>
#include <cstdint>

#define NN 50000
#define NE 800000
#define D  128

static __device__ __forceinline__ float rrelu_f(float x) {
    const float SLOPE = (1.0f/8.0f + 1.0f/3.0f) * 0.5f;
    return x >= 0.0f ? x : x * SLOPE;
}

// ---------------- scratch layout (floats) ----------------
#define ND        (NN * D)                 // 6,400,000
#define OFF_EA    0                        // Eagg 50k x 128
#define OFF_P0    (ND)                     // 50k x 256: [x@Wn0u | x@Wl0]
#define OFF_E0    (3 * ND)                 // EA@Wn0e
#define OFF_E1    (4 * ND)                 // EA@Wn1e
#define OFF_N1    (5 * ND)                 // H1@Wn1u
#define OFF_H1    (6 * ND)                 // gather of h1
#define OFF_PX    (7 * ND)                 // 50k x 256: [h1@Wl1 | h1@Wo_top + bo]
#define OFF_HCAT  (9 * ND)                 // 50k x 256
#define OFF_B2    (11 * ND)                // composite bias [0|bo]
#define OFF_INT   (11 * ND + 256)
#define NI_HIST 0
#define NI_INCL 50176
#define NI_BLK  100352
#define NI_BOFF 100416
#define NI_RP   100480
#define NI_WP   150912
#define NI_PS   201088
#define NI_PE   1001088
#define NI_TOTAL 1801088
#define SCRATCH_N (OFF_INT + NI_TOTAL)

__device__ float g_scratch[SCRATCH_N];

// bf16 weight images: 8 chunks x 64KB ([n][k] bf16 hi then lo).
// 0:Wn0u 1:Wl0 2:Wn0e 3:Wn1e 4:Wl1 5:Wo_top 6:Wn1u 7:Wo_bot
__device__ __align__(16) unsigned char g_bimg[8 * 65536];

// ---------------- PTX helpers ----------------
__device__ __forceinline__ uint32_t smem_u32(const void* p) {
    uint32_t a;
    asm("{ .reg .u64 t; cvta.to.shared.u64 t, %1; cvt.u32.u64 %0, t; }" : "=r"(a) : "l"(p));
    return a;
}

__device__ __forceinline__ void ldsm_x4(uint32_t addr, uint32_t* r) {
    asm volatile("ldmatrix.sync.aligned.m8n8.x4.shared.b16 {%0,%1,%2,%3}, [%4];"
                 : "=r"(r[0]), "=r"(r[1]), "=r"(r[2]), "=r"(r[3]) : "r"(addr));
}

__device__ __forceinline__ void mma_bf16(float* c, const uint32_t* a,
                                         uint32_t b0, uint32_t b1) {
    asm volatile("mma.sync.aligned.m16n8k16.row.col.f32.bf16.bf16.f32 "
                 "{%0,%1,%2,%3}, {%4,%5,%6,%7}, {%8,%9}, {%0,%1,%2,%3};"
                 : "+f"(c[0]), "+f"(c[1]), "+f"(c[2]), "+f"(c[3])
                 : "r"(a[0]), "r"(a[1]), "r"(a[2]), "r"(a[3]), "r"(b0), "r"(b1));
}

// ---------------- CSR build ----------------
__global__ void zero_hist(int* hist) {
    int i = blockIdx.x * blockDim.x + threadIdx.x;
    if (i < NN) hist[i] = 0;
}

__global__ void hist_k(const int* __restrict__ dst, int* __restrict__ hist) {
    int i = blockIdx.x * blockDim.x + threadIdx.x;
    if (i < NE) atomicAdd(hist + __ldg(dst + i), 1);
}

__global__ void scanA(const int* __restrict__ hist, int* __restrict__ incl,
                      int* __restrict__ blk) {
    __shared__ int s[1024];
    int t = threadIdx.x;
    int i = blockIdx.x * 1024 + t;
    int v = (i < NN) ? hist[i] : 0;
    s[t] = v;
    __syncthreads();
#pragma unroll
    for (int off = 1; off < 1024; off <<= 1) {
        int add = (t >= off) ? s[t - off] : 0;
        __syncthreads();
        s[t] += add;
        __syncthreads();
    }
    incl[i] = s[t];
    if (t == 1023) blk[blockIdx.x] = s[t];
}

__global__ void scanB(const int* __restrict__ blk, int* __restrict__ boff) {
    __shared__ int s[64];
    int t = threadIdx.x;
    if (t < 49) s[t] = blk[t];
    __syncthreads();
    if (t == 0) {
        int run = 0;
        for (int b = 0; b < 49; b++) { int v = s[b]; s[b] = run; run += v; }
    }
    __syncthreads();
    if (t < 49) boff[t] = s[t];
}

__global__ void scanC(const int* __restrict__ incl, const int* __restrict__ boff,
                      const int* __restrict__ hist,
                      int* __restrict__ rp, int* __restrict__ wp) {
    int t = threadIdx.x;
    int i = blockIdx.x * 1024 + t;
    if (i < NN) {
        int inc = incl[i] + boff[blockIdx.x];
        rp[i + 1] = inc;
        wp[i] = inc - hist[i];
    }
    if (i == 0) rp[0] = 0;
}

__global__ void permute_k(const int* __restrict__ src, const int* __restrict__ dst,
                          int* __restrict__ wp,
                          int* __restrict__ ps, int* __restrict__ pe) {
    int i = blockIdx.x * blockDim.x + threadIdx.x;
    if (i >= NE) return;
    int d = __ldg(dst + i);
    int pos = atomicAdd(wp + d, 1);
    ps[pos] = __ldg(src + i);
    pe[pos] = i;
}

// ---------------- CSR gathers ----------------
__global__ void gather_e(const float* __restrict__ e,
                         const int* __restrict__ rp,
                         const int* __restrict__ pe,
                         float* __restrict__ EA) {
    int w    = (blockIdx.x * blockDim.x + threadIdx.x) >> 5;
    int lane = threadIdx.x & 31;
    if (w >= NN) return;
    int beg = __ldg(rp + w), end = __ldg(rp + w + 1);
    float4 acc = make_float4(0.f, 0.f, 0.f, 0.f);
    for (int j = beg; j < end; j += 32) {
        int m = min(32, end - j);
        int eid = (lane < m) ? __ldg(pe + j + lane) : 0;
        for (int t = 0; t < m; t++) {
            int et = __shfl_sync(0xffffffffu, eid, t);
            float4 v = *reinterpret_cast<const float4*>(e + (size_t)et * D + lane * 4);
            acc.x += v.x; acc.y += v.y; acc.z += v.z; acc.w += v.w;
        }
    }
    *reinterpret_cast<float4*>(EA + (size_t)w * D + lane * 4) = acc;
}

// O[n] = sum T[src] (T ld ldT), O ld 128
__global__ void gather_T(const float* __restrict__ T, int ldT,
                         const int* __restrict__ rp,
                         const int* __restrict__ ps,
                         float* __restrict__ O) {
    int w    = (blockIdx.x * blockDim.x + threadIdx.x) >> 5;
    int lane = threadIdx.x & 31;
    if (w >= NN) return;
    int beg = __ldg(rp + w), end = __ldg(rp + w + 1);
    float4 acc = make_float4(0.f, 0.f, 0.f, 0.f);
    for (int j = beg; j < end; j += 32) {
        int m = min(32, end - j);
        int sidx = (lane < m) ? __ldg(ps + j + lane) : 0;
        for (int t = 0; t < m; t++) {
            int s = __shfl_sync(0xffffffffu, sidx, t);
            float4 v = *reinterpret_cast<const float4*>(T + (size_t)s * ldT + lane * 4);
            acc.x += v.x; acc.y += v.y; acc.z += v.z; acc.w += v.w;
        }
    }
    *reinterpret_cast<float4*>(O + (size_t)w * D + lane * 4) = acc;
}

// ---------------- fused gather + layer-0 epilogue (from R7) ----------------
// h = rrelu( (sum T[src] + EW[n])/max(cnt,1) + (cnt>0)*bn + Tb[n] + bl )
__global__ void gather_epi(const float* __restrict__ T,    // ld 256, cols 0-127
                           const float* __restrict__ Tb,   // ld 256
                           const float* __restrict__ EW, int ldE,
                           const int* __restrict__ rp,
                           const int* __restrict__ ps,
                           const float* __restrict__ bn,
                           const float* __restrict__ bl,
                           float* __restrict__ hc) {       // ld 256
    int w    = (blockIdx.x * blockDim.x + threadIdx.x) >> 5;
    int lane = threadIdx.x & 31;
    if (w >= NN) return;
    int beg = __ldg(rp + w), end = __ldg(rp + w + 1);
    float4 acc = make_float4(0.f, 0.f, 0.f, 0.f);
    for (int j = beg; j < end; j += 32) {
        int m = min(32, end - j);
        int sidx = (lane < m) ? __ldg(ps + j + lane) : 0;
        for (int t = 0; t < m; t++) {
            int s = __shfl_sync(0xffffffffu, sidx, t);
            float4 v = *reinterpret_cast<const float4*>(T + (size_t)s * 256 + lane * 4);
            acc.x += v.x; acc.y += v.y; acc.z += v.z; acc.w += v.w;
        }
    }
    int cn = end - beg;
    float inv = 1.0f / fmaxf((float)cn, 1.0f);
    float g = (cn > 0) ? 1.0f : 0.0f;
    float4 ew = *reinterpret_cast<const float4*>(EW + (size_t)w * ldE + lane * 4);
    float4 tb = *reinterpret_cast<const float4*>(Tb + (size_t)w * 256 + lane * 4);
    float4 b4 = *reinterpret_cast<const float4*>(bn + lane * 4);
    float4 l4 = *reinterpret_cast<const float4*>(bl + lane * 4);
    float4 o;
    o.x = rrelu_f((acc.x + ew.x) * inv + g * b4.x + tb.x + l4.x);
    o.y = rrelu_f((acc.y + ew.y) * inv + g * b4.y + tb.y + l4.y);
    o.z = rrelu_f((acc.z + ew.z) * inv + g * b4.z + tb.z + l4.z);
    o.w = rrelu_f((acc.w + ew.w) * inv + g * b4.w + tb.w + l4.w);
    *reinterpret_cast<float4*>(hc + (size_t)w * 256 + lane * 4) = o;
}

// ---------------- elementwise layer-1 epilogue ----------------
__global__ void epi_k(const float* __restrict__ Nn,        // ld 128
                      const float* __restrict__ En, int ldE,
                      const float* __restrict__ Sn, int ldS,
                      const int* __restrict__ rp,
                      const float* __restrict__ bn,
                      const float* __restrict__ bl,
                      float* __restrict__ hc) {            // ld 256
    int idx = blockIdx.x * blockDim.x + threadIdx.x;
    if (idx >= ND / 4) return;
    int node = idx >> 5;
    int c4   = (idx & 31) * 4;
    int cn = __ldg(rp + node + 1) - __ldg(rp + node);
    float inv = 1.0f / fmaxf((float)cn, 1.0f);
    float g = (cn > 0) ? 1.0f : 0.0f;
    float4 a = *reinterpret_cast<const float4*>(Nn + (size_t)node * 128 + c4);
    float4 b = *reinterpret_cast<const float4*>(En + (size_t)node * ldE + c4);
    float4 s = *reinterpret_cast<const float4*>(Sn + (size_t)node * ldS + c4);
    float4 b4 = *reinterpret_cast<const float4*>(bn + c4);
    float4 l4 = *reinterpret_cast<const float4*>(bl + c4);
    float4 o;
    o.x = rrelu_f((a.x + b.x) * inv + g * b4.x + s.x + l4.x);
    o.y = rrelu_f((a.y + b.y) * inv + g * b4.y + s.y + l4.y);
    o.z = rrelu_f((a.z + b.z) * inv + g * b4.z + s.z + l4.z);
    o.w = rrelu_f((a.w + b.w) * inv + g * b4.w + s.w + l4.w);
    *reinterpret_cast<float4*>(hc + (size_t)node * 256 + c4) = o;
}

// ---------------- weight image prep (+ composite bias) ----------------
__global__ void prep_B(const float* __restrict__ Wn0, const float* __restrict__ Wl0,
                       const float* __restrict__ Wn1, const float* __restrict__ Wl1,
                       const float* __restrict__ Wo, const float* __restrict__ bo,
                       unsigned char* __restrict__ img, float* __restrict__ bias2) {
    int ci = blockIdx.x;
    int t = threadIdx.x;  // 128
    if (ci == 8) {
        bias2[t] = 0.f;
        bias2[128 + t] = bo[t];
        return;
    }
    const float* W;
    switch (ci) {
        case 0: W = Wn0; break;               // Wn0u
        case 1: W = Wl0; break;
        case 2: W = Wn0 + 128 * 128; break;   // Wn0e
        case 3: W = Wn1 + 128 * 128; break;   // Wn1e
        case 4: W = Wl1; break;
        case 5: W = Wo; break;                // Wo_top
        case 6: W = Wn1; break;               // Wn1u
        default: W = Wo + 128 * 128; break;   // Wo_bot
    }
    unsigned char* hi_img = img + ci * 65536;
    unsigned char* lo_img = hi_img + 32768;

    __shared__ float sw[64][129];
    for (int kt = 0; kt < 2; kt++) {
        for (int i = t; i < 64 * 128; i += 128)
            sw[i >> 7][i & 127] = W[kt * 64 * 128 + i];
        __syncthreads();
        int n = t;
#pragma unroll
        for (int u = 0; u < 8; u++) {
            union { __nv_bfloat16 h[8]; uint4 v; } hi;
            union { __nv_bfloat16 h[8]; uint4 v; } lo;
#pragma unroll
            for (int j = 0; j < 8; j++) {
                float f = sw[u * 8 + j][n];
                __nv_bfloat16 hb = __float2bfloat16(f);
                hi.h[j] = hb;
                lo.h[j] = __float2bfloat16(f - __bfloat162float(hb));
            }
            uint32_t off = (uint32_t)(n * 256 + kt * 128 + u * 16);
            *reinterpret_cast<uint4*>(hi_img + off) = hi.v;
            *reinterpret_cast<uint4*>(lo_img + off) = lo.v;
        }
        __syncthreads();
    }
}

// ---------------- HMMA bf16x3 GEMM: 128 x (128*NCH) tile, K=128, 512 thr ----
#define SA_HI 0
#define SA_LO 34816
#define SB_BASE 69632
#define CHUNK_SM 69632
#define SM_SZ(NCH) (SB_BASE + (NCH) * CHUNK_SM)

template<int NCH>
__global__ __launch_bounds__(512, 1)
void gemm_mma(const float* __restrict__ A, int lda,
              const unsigned char* __restrict__ Bimg,
              float* __restrict__ C, int ldc,
              const float* __restrict__ bias,
              const float* __restrict__ Cin, int ldcin, int M) {
    constexpr int MI = 2 * NCH;
    constexpr int NW = 4 * NCH;
    extern __shared__ unsigned char smem[];
    uint32_t sb = smem_u32(smem);
    int tid  = threadIdx.x;
    int lane = tid & 31;
    int wid  = tid >> 5;
    int wn   = wid % NW;
    int wm   = wid / NW;
    int bm   = blockIdx.y * 128;

    float acc[MI][4][4];
#pragma unroll
    for (int mi = 0; mi < MI; mi++)
#pragma unroll
        for (int ni = 0; ni < 4; ni++)
#pragma unroll
            for (int q = 0; q < 4; q++) acc[mi][ni][q] = 0.f;

    {
        int r = tid >> 2;
        int q = tid & 3;
        bool valid = (bm + r) < M;
        const float4* ap = reinterpret_cast<const float4*>(
            A + (size_t)(bm + r) * lda + q * 32);
        float4 z4 = make_float4(0.f, 0.f, 0.f, 0.f);
#pragma unroll
        for (int u = 0; u < 4; u++) {
            float4 f0 = valid ? ap[u * 2]     : z4;
            float4 f1 = valid ? ap[u * 2 + 1] : z4;
            float fs[8] = {f0.x, f0.y, f0.z, f0.w, f1.x, f1.y, f1.z, f1.w};
            union { __nv_bfloat16 b[8]; uint4 v; } hi;
            union { __nv_bfloat16 b[8]; uint4 v; } lo;
#pragma unroll
            for (int j = 0; j < 8; j++) {
                __nv_bfloat16 hb = __float2bfloat16(fs[j]);
                hi.b[j] = hb;
                lo.b[j] = __float2bfloat16(fs[j] - __bfloat162float(hb));
            }
            uint32_t off = (uint32_t)(r * 272 + q * 64 + u * 16);
            *reinterpret_cast<uint4*>(smem + SA_HI + off) = hi.v;
            *reinterpret_cast<uint4*>(smem + SA_LO + off) = lo.v;
        }
    }
#pragma unroll
    for (int c = 0; c < NCH; c++) {
        const unsigned char* ch = Bimg + (size_t)(blockIdx.x * NCH + c) * 65536;
        unsigned char* db = smem + SB_BASE + c * CHUNK_SM;
#pragma unroll
        for (int i = 0; i < 4; i++) {
            int linear = tid + i * 512;
            int row = linear >> 4;
            int c16 = linear & 15;
            uint32_t soff = (uint32_t)(row * 256 + c16 * 16);
            uint32_t doff = (uint32_t)(row * 272 + c16 * 16);
            *reinterpret_cast<uint4*>(db + doff) =
                *reinterpret_cast<const uint4*>(ch + soff);
            *reinterpret_cast<uint4*>(db + 34816 + doff) =
                *reinterpret_cast<const uint4*>(ch + 32768 + soff);
        }
    }
    __syncthreads();

    uint32_t a_row = (uint32_t)(wm * (32 * NCH) + (lane & 15));
    uint32_t a_cb  = (uint32_t)((lane >> 4) * 16);
    uint32_t sbB   = sb + SB_BASE + (wn >> 2) * CHUNK_SM;
    uint32_t b_n   = (uint32_t)((wn & 3) * 32 + ((lane >> 4) << 3) + (lane & 7));
    uint32_t b_cb  = (uint32_t)(((lane >> 3) & 1) * 16);
#pragma unroll
    for (int ks = 0; ks < 8; ks++) {
        uint32_t kb = (uint32_t)(ks * 32);
        uint32_t Ahi[MI][4], Alo[MI][4];
#pragma unroll
        for (int mi = 0; mi < MI; mi++) {
            ldsm_x4(sb + SA_HI + (a_row + mi * 16) * 272 + kb + a_cb, Ahi[mi]);
            ldsm_x4(sb + SA_LO + (a_row + mi * 16) * 272 + kb + a_cb, Alo[mi]);
        }
#pragma unroll
        for (int nj = 0; nj < 2; nj++) {
            uint32_t bh[4], bl[4];
            uint32_t baddr = (b_n + nj * 16) * 272 + kb + b_cb;
            ldsm_x4(sbB + baddr, bh);
            ldsm_x4(sbB + 34816 + baddr, bl);
#pragma unroll
            for (int mi = 0; mi < MI; mi++) {
                mma_bf16(acc[mi][2 * nj],     Ahi[mi], bh[0], bh[1]);
                mma_bf16(acc[mi][2 * nj],     Ahi[mi], bl[0], bl[1]);
                mma_bf16(acc[mi][2 * nj],     Alo[mi], bh[0], bh[1]);
                mma_bf16(acc[mi][2 * nj + 1], Ahi[mi], bh[2], bh[3]);
                mma_bf16(acc[mi][2 * nj + 1], Ahi[mi], bl[2], bl[3]);
                mma_bf16(acc[mi][2 * nj + 1], Alo[mi], bh[2], bh[3]);
            }
        }
    }

    int lrow = lane >> 2;
    int lcol = (lane & 3) * 2;
#pragma unroll
    for (int mi = 0; mi < MI; mi++) {
        int row0 = bm + wm * (32 * NCH) + mi * 16 + lrow;
#pragma unroll
        for (int ni = 0; ni < 4; ni++) {
            int gcol = blockIdx.x * (128 * NCH) + wn * 32 + ni * 8 + lcol;
            float b0 = 0.f, b1 = 0.f;
            if (bias) {
                b0 = __ldg(bias + gcol);
                b1 = __ldg(bias + gcol + 1);
            }
            if (row0 < M) {
                float* cp = C + (size_t)row0 * ldc + gcol;
                float2 v = make_float2(acc[mi][ni][0] + b0, acc[mi][ni][1] + b1);
                if (Cin) {
                    const float* ip = Cin + (size_t)row0 * ldcin + gcol;
                    v.x += ip[0]; v.y += ip[1];
                }
                *reinterpret_cast<float2*>(cp) = v;
            }
            if (row0 + 8 < M) {
                float* cp = C + (size_t)(row0 + 8) * ldc + gcol;
                float2 v = make_float2(acc[mi][ni][2] + b0, acc[mi][ni][3] + b1);
                if (Cin) {
                    const float* ip = Cin + (size_t)(row0 + 8) * ldcin + gcol;
                    v.x += ip[0]; v.y += ip[1];
                }
                *reinterpret_cast<float2*>(cp) = v;
            }
        }
    }
}

// ---------------- launch ----------------
extern "C" void kernel_launch(void* const* d_in, const int* in_sizes, int n_in,
                              void* d_out, int out_size) {
    const float* x   = (const float*)d_in[0];
    const float* e   = (const float*)d_in[1];
    const int*   src = (const int*)d_in[2];
    const int*   dst = (const int*)d_in[3];
    const float* Wn0 = (const float*)d_in[4];
    const float* bn0 = (const float*)d_in[5];
    const float* Wl0 = (const float*)d_in[6];
    const float* bl0 = (const float*)d_in[7];
    const float* Wn1 = (const float*)d_in[8];
    const float* bn1 = (const float*)d_in[9];
    const float* Wl1 = (const float*)d_in[10];
    const float* bl1 = (const float*)d_in[11];
    const float* Wo  = (const float*)d_in[12];
    const float* bo  = (const float*)d_in[13];
    float* out = (float*)d_out;

    float* S = nullptr;
    cudaGetSymbolAddress((void**)&S, g_scratch);
    unsigned char* BI = nullptr;
    cudaGetSymbolAddress((void**)&BI, g_bimg);

    float* EA   = S + OFF_EA;
    float* P0   = S + OFF_P0;
    float* E0   = S + OFF_E0;
    float* E1   = S + OFF_E1;
    float* N1   = S + OFF_N1;
    float* H1   = S + OFF_H1;
    float* PX   = S + OFF_PX;
    float* HCAT = S + OFF_HCAT;
    float* B2   = S + OFF_B2;
    int*   I    = (int*)(S + OFF_INT);
    int* hist = I + NI_HIST;
    int* incl = I + NI_INCL;
    int* blk  = I + NI_BLK;
    int* boff = I + NI_BOFF;
    int* rp   = I + NI_RP;
    int* wp   = I + NI_WP;
    int* ps   = I + NI_PS;
    int* pe   = I + NI_PE;

    static cudaStream_t s1 = nullptr;
    static cudaEvent_t evRoot, evPrep, evE, evE0, evN1;
    if (!s1) {
        cudaStreamCreateWithFlags(&s1, cudaStreamNonBlocking);
        cudaEventCreateWithFlags(&evRoot, cudaEventDisableTiming);
        cudaEventCreateWithFlags(&evPrep, cudaEventDisableTiming);
        cudaEventCreateWithFlags(&evE,    cudaEventDisableTiming);
        cudaEventCreateWithFlags(&evE0,   cudaEventDisableTiming);
        cudaEventCreateWithFlags(&evN1,   cudaEventDisableTiming);
    }

    cudaFuncSetAttribute(gemm_mma<2>,
                         cudaFuncAttributeMaxDynamicSharedMemorySize, SM_SZ(2));
    cudaFuncSetAttribute(gemm_mma<1>,
                         cudaFuncAttributeMaxDynamicSharedMemorySize, SM_SZ(1));

    const int MT = (NN + 127) / 128;
    const dim3 GT(1, MT);
    const int GW = (NN * 32 + 255) / 256;
    const int EPB = (ND / 4 + 255) / 256;

    // fork root
    cudaEventRecord(evRoot, 0);
    cudaStreamWaitEvent(s1, evRoot, 0);

    // s1: CSR build + edge-feature gather
    zero_hist<<<(NN + 255) / 256, 256, 0, s1>>>(hist);
    hist_k<<<(NE + 255) / 256, 256, 0, s1>>>(dst, hist);
    scanA<<<49, 1024, 0, s1>>>(hist, incl, blk);
    scanB<<<1, 64, 0, s1>>>(blk, boff);
    scanC<<<49, 1024, 0, s1>>>(incl, boff, hist, rp, wp);
    permute_k<<<(NE + 255) / 256, 256, 0, s1>>>(src, dst, wp, ps, pe);
    gather_e<<<GW, 256, 0, s1>>>(e, rp, pe, EA);
    cudaEventRecord(evE, s1);

    // s0: weight images; G1: x @ [Wn0u | Wl0] -> P0
    prep_B<<<9, 128>>>(Wn0, Wl0, Wn1, Wl1, Wo, bo, BI, B2);
    cudaEventRecord(evPrep, 0);
    gemm_mma<2><<<GT, 512, SM_SZ(2)>>>(x, D, BI + 0 * 65536, P0, 256, nullptr, nullptr, 0, NN);

    // s0: G2a: EA @ Wn0e -> E0 (critical half only)
    cudaStreamWaitEvent(0, evE, 0);
    gemm_mma<1><<<GT, 512, SM_SZ(1)>>>(EA, D, BI + 2 * 65536, E0, 128, nullptr, nullptr, 0, NN);

    // s1: G2b: EA @ Wn1e -> E1 (off critical path; overlaps G2a/epi0)
    cudaStreamWaitEvent(s1, evPrep, 0);
    gemm_mma<1><<<GT, 512, SM_SZ(1), s1>>>(EA, D, BI + 3 * 65536, E1, 128, nullptr, nullptr, 0, NN);

    // s0: fused gather + epilogue layer 0 -> h1 (HCAT cols 0-127)
    gather_epi<<<GW, 256>>>(P0, P0 + 128, E0, 128, rp, ps, bn0, bl0, HCAT);
    cudaEventRecord(evE0, 0);

    // s1: gather_h1 -> H1; N1 = H1 @ Wn1u   (overlaps s0's PX)
    cudaStreamWaitEvent(s1, evE0, 0);
    gather_T<<<GW, 256, 0, s1>>>(HCAT, 256, rp, ps, H1);
    gemm_mma<1><<<GT, 512, SM_SZ(1), s1>>>(H1, D, BI + 6 * 65536, N1, 128, nullptr, nullptr, 0, NN);
    cudaEventRecord(evN1, s1);

    // s0: PX = h1 @ [Wl1 | Wo_top] + [0|bo]   (wide, shares A-load)
    gemm_mma<2><<<GT, 512, SM_SZ(2)>>>(HCAT, 256, BI + 4 * 65536, PX, 256, B2, nullptr, 0, NN);

    // s0: epi1 (elementwise) -> h2 (HCAT cols 128-255)
    cudaStreamWaitEvent(0, evN1, 0);
    epi_k<<<EPB, 256>>>(N1, E1, 128, PX, 256, rp, bn1, bl1, HCAT + 128);

    // s0: out = h2 @ Wo_bot + PX_right
    gemm_mma<1><<<GT, 512, SM_SZ(1)>>>(HCAT + 128, 256, BI + 7 * 65536, out, 128,
                                       nullptr, PX + 128, 256, NN);
}

// round 12
// speedup vs baseline: 1.4648x; 1.0202x over previous
#include <cuda_runtime.h>
#include <cuda_bf16.h>
#include <cstdint>

#define NN 50000
#define NE 800000
#define D  128
#define NSPLIT 25088   // 196 row-tiles

static __device__ __forceinline__ float rrelu_f(float x) {
    const float SLOPE = (1.0f/8.0f + 1.0f/3.0f) * 0.5f;
    return x >= 0.0f ? x : x * SLOPE;
}

// ---------------- scratch layout (floats) ----------------
#define ND        (NN * D)                 // 6,400,000
#define OFF_EA    0                        // Eagg 50k x 128
#define OFF_PE    (ND)                     // 50k x 256: [E0 | E1]
#define OFF_P0    (3 * ND)                 // 50k x 256: [x@Wn0u | x@Wl0]
#define OFF_P1    (5 * ND)                 // 50k x 256: [h1@Wn1u | h1@Wl1]
#define OFF_HCAT  (7 * ND)                 // 50k x 256
#define OFF_INT   (9 * ND)
#define NI_HIST 0
#define NI_INCL 50176
#define NI_BLK  100352
#define NI_BOFF 100416
#define NI_RP   100480
#define NI_WP   150912
#define NI_PS   201088
#define NI_PE   1001088
#define NI_TOTAL 1801088
#define SCRATCH_N (OFF_INT + NI_TOTAL)

__device__ float g_scratch[SCRATCH_N];

// bf16 weight images: 8 chunks x 64KB ([n][k] bf16 hi then lo).
// 0:Wn0u 1:Wl0 2:Wn0e 3:Wn1e 4:Wn1u 5:Wl1 6:Wo_top 7:Wo_bot
__device__ __align__(16) unsigned char g_bimg[8 * 65536];

// ---------------- PTX helpers ----------------
__device__ __forceinline__ uint32_t smem_u32(const void* p) {
    uint32_t a;
    asm("{ .reg .u64 t; cvta.to.shared.u64 t, %1; cvt.u32.u64 %0, t; }" : "=r"(a) : "l"(p));
    return a;
}

__device__ __forceinline__ void ldsm_x4(uint32_t addr, uint32_t* r) {
    asm volatile("ldmatrix.sync.aligned.m8n8.x4.shared.b16 {%0,%1,%2,%3}, [%4];"
                 : "=r"(r[0]), "=r"(r[1]), "=r"(r[2]), "=r"(r[3]) : "r"(addr));
}

__device__ __forceinline__ void mma_bf16(float* c, const uint32_t* a,
                                         uint32_t b0, uint32_t b1) {
    asm volatile("mma.sync.aligned.m16n8k16.row.col.f32.bf16.bf16.f32 "
                 "{%0,%1,%2,%3}, {%4,%5,%6,%7}, {%8,%9}, {%0,%1,%2,%3};"
                 : "+f"(c[0]), "+f"(c[1]), "+f"(c[2]), "+f"(c[3])
                 : "r"(a[0]), "r"(a[1]), "r"(a[2]), "r"(a[3]), "r"(b0), "r"(b1));
}

// ---------------- CSR build ----------------
__global__ void zero_hist(int* hist) {
    int i = blockIdx.x * blockDim.x + threadIdx.x;
    if (i < NN) hist[i] = 0;
}

__global__ void hist_k(const int* __restrict__ dst, int* __restrict__ hist) {
    int i = blockIdx.x * blockDim.x + threadIdx.x;
    if (i < NE) atomicAdd(hist + __ldg(dst + i), 1);
}

__global__ void scanA(const int* __restrict__ hist, int* __restrict__ incl,
                      int* __restrict__ blk) {
    __shared__ int s[1024];
    int t = threadIdx.x;
    int i = blockIdx.x * 1024 + t;
    int v = (i < NN) ? hist[i] : 0;
    s[t] = v;
    __syncthreads();
#pragma unroll
    for (int off = 1; off < 1024; off <<= 1) {
        int add = (t >= off) ? s[t - off] : 0;
        __syncthreads();
        s[t] += add;
        __syncthreads();
    }
    incl[i] = s[t];
    if (t == 1023) blk[blockIdx.x] = s[t];
}

__global__ void scanB(const int* __restrict__ blk, int* __restrict__ boff) {
    __shared__ int s[64];
    int t = threadIdx.x;
    if (t < 49) s[t] = blk[t];
    __syncthreads();
    if (t == 0) {
        int run = 0;
        for (int b = 0; b < 49; b++) { int v = s[b]; s[b] = run; run += v; }
    }
    __syncthreads();
    if (t < 49) boff[t] = s[t];
}

__global__ void scanC(const int* __restrict__ incl, const int* __restrict__ boff,
                      const int* __restrict__ hist,
                      int* __restrict__ rp, int* __restrict__ wp) {
    int t = threadIdx.x;
    int i = blockIdx.x * 1024 + t;
    if (i < NN) {
        int inc = incl[i] + boff[blockIdx.x];
        rp[i + 1] = inc;
        wp[i] = inc - hist[i];
    }
    if (i == 0) rp[0] = 0;
}

__global__ void permute_k(const int* __restrict__ src, const int* __restrict__ dst,
                          int* __restrict__ wp,
                          int* __restrict__ ps, int* __restrict__ pe) {
    int i = blockIdx.x * blockDim.x + threadIdx.x;
    if (i >= NE) return;
    int d = __ldg(dst + i);
    int pos = atomicAdd(wp + d, 1);
    ps[pos] = __ldg(src + i);
    pe[pos] = i;
}

// ---------------- CSR gathers ----------------
// Eagg[n] = sum e[eid], for nodes in [n0, n1)
__global__ void gather_e(const float* __restrict__ e,
                         const int* __restrict__ rp,
                         const int* __restrict__ pe,
                         float* __restrict__ Eagg, int n0, int n1) {
    int w    = n0 + ((blockIdx.x * blockDim.x + threadIdx.x) >> 5);
    int lane = threadIdx.x & 31;
    if (w >= n1) return;
    int beg = __ldg(rp + w), end = __ldg(rp + w + 1);
    float4 acc = make_float4(0.f, 0.f, 0.f, 0.f);
    for (int j = beg; j < end; j += 32) {
        int m = min(32, end - j);
        int eid = (lane < m) ? __ldg(pe + j + lane) : 0;
        for (int t = 0; t < m; t++) {
            int et = __shfl_sync(0xffffffffu, eid, t);
            float4 v = *reinterpret_cast<const float4*>(e + (size_t)et * D + lane * 4);
            acc.x += v.x; acc.y += v.y; acc.z += v.z; acc.w += v.w;
        }
    }
    *reinterpret_cast<float4*>(Eagg + (size_t)w * D + lane * 4) = acc;
}

// ---------------- fused gather + layer epilogue ----------------
// h = rrelu( (sum T[src] + EW[n])/max(cnt,1) + (cnt>0)*bn + Tb[n] + bl )
__global__ void gather_epi(const float* __restrict__ T,    // ld 256, cols 0-127
                           const float* __restrict__ Tb,   // ld 256
                           const float* __restrict__ EW,   // ld 256
                           const int* __restrict__ rp,
                           const int* __restrict__ ps,
                           const float* __restrict__ bn,
                           const float* __restrict__ bl,
                           float* __restrict__ hc) {       // ld 256
    int w    = (blockIdx.x * blockDim.x + threadIdx.x) >> 5;
    int lane = threadIdx.x & 31;
    if (w >= NN) return;
    int beg = __ldg(rp + w), end = __ldg(rp + w + 1);
    float4 acc = make_float4(0.f, 0.f, 0.f, 0.f);
    for (int j = beg; j < end; j += 32) {
        int m = min(32, end - j);
        int sidx = (lane < m) ? __ldg(ps + j + lane) : 0;
        for (int t = 0; t < m; t++) {
            int s = __shfl_sync(0xffffffffu, sidx, t);
            float4 v = *reinterpret_cast<const float4*>(T + (size_t)s * 256 + lane * 4);
            acc.x += v.x; acc.y += v.y; acc.z += v.z; acc.w += v.w;
        }
    }
    int cn = end - beg;
    float inv = 1.0f / fmaxf((float)cn, 1.0f);
    float g = (cn > 0) ? 1.0f : 0.0f;
    float4 ew = *reinterpret_cast<const float4*>(EW + (size_t)w * 256 + lane * 4);
    float4 tb = *reinterpret_cast<const float4*>(Tb + (size_t)w * 256 + lane * 4);
    float4 b4 = *reinterpret_cast<const float4*>(bn + lane * 4);
    float4 l4 = *reinterpret_cast<const float4*>(bl + lane * 4);
    float4 o;
    o.x = rrelu_f((acc.x + ew.x) * inv + g * b4.x + tb.x + l4.x);
    o.y = rrelu_f((acc.y + ew.y) * inv + g * b4.y + tb.y + l4.y);
    o.z = rrelu_f((acc.z + ew.z) * inv + g * b4.z + tb.z + l4.z);
    o.w = rrelu_f((acc.w + ew.w) * inv + g * b4.w + tb.w + l4.w);
    *reinterpret_cast<float4*>(hc + (size_t)w * 256 + lane * 4) = o;
}

// ---------------- weight image prep ----------------
__global__ void prep_B(const float* __restrict__ Wn0, const float* __restrict__ Wl0,
                       const float* __restrict__ Wn1, const float* __restrict__ Wl1,
                       const float* __restrict__ Wo, unsigned char* __restrict__ img) {
    int ci = blockIdx.x;
    const float* W;
    switch (ci) {
        case 0: W = Wn0; break;               // Wn0u
        case 1: W = Wl0; break;
        case 2: W = Wn0 + 128 * 128; break;   // Wn0e
        case 3: W = Wn1 + 128 * 128; break;   // Wn1e
        case 4: W = Wn1; break;               // Wn1u
        case 5: W = Wl1; break;
        case 6: W = Wo; break;
        default: W = Wo + 128 * 128; break;
    }
    unsigned char* hi_img = img + ci * 65536;
    unsigned char* lo_img = hi_img + 32768;

    __shared__ float sw[64][129];
    int t = threadIdx.x;  // 128
    for (int kt = 0; kt < 2; kt++) {
        for (int i = t; i < 64 * 128; i += 128)
            sw[i >> 7][i & 127] = W[kt * 64 * 128 + i];
        __syncthreads();
        int n = t;
#pragma unroll
        for (int u = 0; u < 8; u++) {
            union { __nv_bfloat16 h[8]; uint4 v; } hi;
            union { __nv_bfloat16 h[8]; uint4 v; } lo;
#pragma unroll
            for (int j = 0; j < 8; j++) {
                float f = sw[u * 8 + j][n];
                __nv_bfloat16 hb = __float2bfloat16(f);
                hi.h[j] = hb;
                lo.h[j] = __float2bfloat16(f - __bfloat162float(hb));
            }
            uint32_t off = (uint32_t)(n * 256 + kt * 128 + u * 16);
            *reinterpret_cast<uint4*>(hi_img + off) = hi.v;
            *reinterpret_cast<uint4*>(lo_img + off) = lo.v;
        }
        __syncthreads();
    }
}

// ---------------- HMMA bf16x3 GEMM: 128 x (128*NCH) tile, K=128, 512 thr ----
#define SA_HI 0
#define SA_LO 34816
#define SB_BASE 69632
#define CHUNK_SM 69632
#define SM_SZ(NCH) (SB_BASE + (NCH) * CHUNK_SM)

template<int NCH>
__global__ __launch_bounds__(512, 1)
void gemm_mma(const float* __restrict__ A, int lda,
              const unsigned char* __restrict__ Bimg,
              float* __restrict__ C, int ldc,
              const float* __restrict__ bias, int accumulate, int M) {
    constexpr int MI = 2 * NCH;
    constexpr int NW = 4 * NCH;
    extern __shared__ unsigned char smem[];
    uint32_t sb = smem_u32(smem);
    int tid  = threadIdx.x;
    int lane = tid & 31;
    int wid  = tid >> 5;
    int wn   = wid % NW;
    int wm   = wid / NW;
    int bm   = blockIdx.y * 128;

    float acc[MI][4][4];
#pragma unroll
    for (int mi = 0; mi < MI; mi++)
#pragma unroll
        for (int ni = 0; ni < 4; ni++)
#pragma unroll
            for (int q = 0; q < 4; q++) acc[mi][ni][q] = 0.f;

    {
        int r = tid >> 2;
        int q = tid & 3;
        bool valid = (bm + r) < M;
        const float4* ap = reinterpret_cast<const float4*>(
            A + (size_t)(bm + r) * lda + q * 32);
        float4 z4 = make_float4(0.f, 0.f, 0.f, 0.f);
#pragma unroll
        for (int u = 0; u < 4; u++) {
            float4 f0 = valid ? ap[u * 2]     : z4;
            float4 f1 = valid ? ap[u * 2 + 1] : z4;
            float fs[8] = {f0.x, f0.y, f0.z, f0.w, f1.x, f1.y, f1.z, f1.w};
            union { __nv_bfloat16 b[8]; uint4 v; } hi;
            union { __nv_bfloat16 b[8]; uint4 v; } lo;
#pragma unroll
            for (int j = 0; j < 8; j++) {
                __nv_bfloat16 hb = __float2bfloat16(fs[j]);
                hi.b[j] = hb;
                lo.b[j] = __float2bfloat16(fs[j] - __bfloat162float(hb));
            }
            uint32_t off = (uint32_t)(r * 272 + q * 64 + u * 16);
            *reinterpret_cast<uint4*>(smem + SA_HI + off) = hi.v;
            *reinterpret_cast<uint4*>(smem + SA_LO + off) = lo.v;
        }
    }
#pragma unroll
    for (int c = 0; c < NCH; c++) {
        const unsigned char* ch = Bimg + (size_t)(blockIdx.x * NCH + c) * 65536;
        unsigned char* db = smem + SB_BASE + c * CHUNK_SM;
#pragma unroll
        for (int i = 0; i < 4; i++) {
            int linear = tid + i * 512;
            int row = linear >> 4;
            int c16 = linear & 15;
            uint32_t soff = (uint32_t)(row * 256 + c16 * 16);
            uint32_t doff = (uint32_t)(row * 272 + c16 * 16);
            *reinterpret_cast<uint4*>(db + doff) =
                *reinterpret_cast<const uint4*>(ch + soff);
            *reinterpret_cast<uint4*>(db + 34816 + doff) =
                *reinterpret_cast<const uint4*>(ch + 32768 + soff);
        }
    }
    __syncthreads();

    uint32_t a_row = (uint32_t)(wm * (32 * NCH) + (lane & 15));
    uint32_t a_cb  = (uint32_t)((lane >> 4) * 16);
    uint32_t sbB   = sb + SB_BASE + (wn >> 2) * CHUNK_SM;
    uint32_t b_n   = (uint32_t)((wn & 3) * 32 + ((lane >> 4) << 3) + (lane & 7));
    uint32_t b_cb  = (uint32_t)(((lane >> 3) & 1) * 16);
#pragma unroll
    for (int ks = 0; ks < 8; ks++) {
        uint32_t kb = (uint32_t)(ks * 32);
        uint32_t Ahi[MI][4], Alo[MI][4];
#pragma unroll
        for (int mi = 0; mi < MI; mi++) {
            ldsm_x4(sb + SA_HI + (a_row + mi * 16) * 272 + kb + a_cb, Ahi[mi]);
            ldsm_x4(sb + SA_LO + (a_row + mi * 16) * 272 + kb + a_cb, Alo[mi]);
        }
#pragma unroll
        for (int nj = 0; nj < 2; nj++) {
            uint32_t bh[4], bl[4];
            uint32_t baddr = (b_n + nj * 16) * 272 + kb + b_cb;
            ldsm_x4(sbB + baddr, bh);
            ldsm_x4(sbB + 34816 + baddr, bl);
#pragma unroll
            for (int mi = 0; mi < MI; mi++) {
                mma_bf16(acc[mi][2 * nj],     Ahi[mi], bh[0], bh[1]);
                mma_bf16(acc[mi][2 * nj],     Ahi[mi], bl[0], bl[1]);
                mma_bf16(acc[mi][2 * nj],     Alo[mi], bh[0], bh[1]);
                mma_bf16(acc[mi][2 * nj + 1], Ahi[mi], bh[2], bh[3]);
                mma_bf16(acc[mi][2 * nj + 1], Ahi[mi], bl[2], bl[3]);
                mma_bf16(acc[mi][2 * nj + 1], Alo[mi], bh[2], bh[3]);
            }
        }
    }

    int lrow = lane >> 2;
    int lcol = (lane & 3) * 2;
#pragma unroll
    for (int mi = 0; mi < MI; mi++) {
        int row0 = bm + wm * (32 * NCH) + mi * 16 + lrow;
#pragma unroll
        for (int ni = 0; ni < 4; ni++) {
            int gcol = blockIdx.x * (128 * NCH) + wn * 32 + ni * 8 + lcol;
            float b0 = 0.f, b1 = 0.f;
            if (bias) {
                b0 = __ldg(bias + gcol);
                b1 = __ldg(bias + gcol + 1);
            }
            if (row0 < M) {
                float* cp = C + (size_t)row0 * ldc + gcol;
                float2 v = make_float2(acc[mi][ni][0] + b0, acc[mi][ni][1] + b1);
                if (accumulate) { float2 o = *reinterpret_cast<float2*>(cp); v.x += o.x; v.y += o.y; }
                *reinterpret_cast<float2*>(cp) = v;
            }
            if (row0 + 8 < M) {
                float* cp = C + (size_t)(row0 + 8) * ldc + gcol;
                float2 v = make_float2(acc[mi][ni][2] + b0, acc[mi][ni][3] + b1);
                if (accumulate) { float2 o = *reinterpret_cast<float2*>(cp); v.x += o.x; v.y += o.y; }
                *reinterpret_cast<float2*>(cp) = v;
            }
        }
    }
}

// ---------------- launch ----------------
extern "C" void kernel_launch(void* const* d_in, const int* in_sizes, int n_in,
                              void* d_out, int out_size) {
    const float* x   = (const float*)d_in[0];
    const float* e   = (const float*)d_in[1];
    const int*   src = (const int*)d_in[2];
    const int*   dst = (const int*)d_in[3];
    const float* Wn0 = (const float*)d_in[4];
    const float* bn0 = (const float*)d_in[5];
    const float* Wl0 = (const float*)d_in[6];
    const float* bl0 = (const float*)d_in[7];
    const float* Wn1 = (const float*)d_in[8];
    const float* bn1 = (const float*)d_in[9];
    const float* Wl1 = (const float*)d_in[10];
    const float* bl1 = (const float*)d_in[11];
    const float* Wo  = (const float*)d_in[12];
    const float* bo  = (const float*)d_in[13];
    float* out = (float*)d_out;

    float* S = nullptr;
    cudaGetSymbolAddress((void**)&S, g_scratch);
    unsigned char* BI = nullptr;
    cudaGetSymbolAddress((void**)&BI, g_bimg);

    float* EA   = S + OFF_EA;
    float* PE   = S + OFF_PE;
    float* P0   = S + OFF_P0;
    float* P1   = S + OFF_P1;
    float* HCAT = S + OFF_HCAT;
    int*   I    = (int*)(S + OFF_INT);
    int* hist = I + NI_HIST;
    int* incl = I + NI_INCL;
    int* blk  = I + NI_BLK;
    int* boff = I + NI_BOFF;
    int* rp   = I + NI_RP;
    int* wp   = I + NI_WP;
    int* ps   = I + NI_PS;
    int* pe   = I + NI_PE;

    static cudaStream_t s1 = nullptr;
    static cudaEvent_t evRoot, evE1, evE2, evH0, evG4a;
    if (!s1) {
        cudaStreamCreateWithFlags(&s1, cudaStreamNonBlocking);
        cudaEventCreateWithFlags(&evRoot, cudaEventDisableTiming);
        cudaEventCreateWithFlags(&evE1,   cudaEventDisableTiming);
        cudaEventCreateWithFlags(&evE2,   cudaEventDisableTiming);
        cudaEventCreateWithFlags(&evH0,   cudaEventDisableTiming);
        cudaEventCreateWithFlags(&evG4a,  cudaEventDisableTiming);
    }

    cudaFuncSetAttribute(gemm_mma<2>,
                         cudaFuncAttributeMaxDynamicSharedMemorySize, SM_SZ(2));
    cudaFuncSetAttribute(gemm_mma<1>,
                         cudaFuncAttributeMaxDynamicSharedMemorySize, SM_SZ(1));

    const int MT  = (NN + 127) / 128;   // 391 m-tiles
    const int MT1 = NSPLIT / 128;       // 196
    const int MT2 = MT - MT1;           // 195
    const dim3 GT(1, MT);
    const int GW  = (NN * 32 + 255) / 256;
    const int GW1 = (NSPLIT * 32 + 255) / 256;
    const int GW2 = ((NN - NSPLIT) * 32 + 255) / 256;

    // fork root
    cudaEventRecord(evRoot, 0);
    cudaStreamWaitEvent(s1, evRoot, 0);

    // s1: CSR build + edge-feature gather, split into node halves
    zero_hist<<<(NN + 255) / 256, 256, 0, s1>>>(hist);
    hist_k<<<(NE + 255) / 256, 256, 0, s1>>>(dst, hist);
    scanA<<<49, 1024, 0, s1>>>(hist, incl, blk);
    scanB<<<1, 64, 0, s1>>>(blk, boff);
    scanC<<<49, 1024, 0, s1>>>(incl, boff, hist, rp, wp);
    permute_k<<<(NE + 255) / 256, 256, 0, s1>>>(src, dst, wp, ps, pe);
    gather_e<<<GW1, 256, 0, s1>>>(e, rp, pe, EA, 0, NSPLIT);
    cudaEventRecord(evE1, s1);
    gather_e<<<GW2, 256, 0, s1>>>(e, rp, pe, EA, NSPLIT, NN);
    cudaEventRecord(evE2, s1);

    // s0: weight images, G1: x @ [Wn0u | Wl0] -> P0
    prep_B<<<8, 128>>>(Wn0, Wl0, Wn1, Wl1, Wo, BI);
    gemm_mma<2><<<GT, 512, SM_SZ(2)>>>(x, D, BI + 0 * 65536, P0, 256, nullptr, 0, NN);

    // s0: G2 half-1 (rows 0..NSPLIT) — overlaps gather_e half-2 on s1
    cudaStreamWaitEvent(0, evE1, 0);
    gemm_mma<2><<<dim3(1, MT1), 512, SM_SZ(2)>>>(EA, D, BI + 2 * 65536, PE, 256,
                                                 nullptr, 0, NSPLIT);
    // s0: G2 half-2 (rows NSPLIT..NN)
    cudaStreamWaitEvent(0, evE2, 0);
    gemm_mma<2><<<dim3(1, MT2), 512, SM_SZ(2)>>>(EA + (size_t)NSPLIT * D, D,
                                                 BI + 2 * 65536,
                                                 PE + (size_t)NSPLIT * 256, 256,
                                                 nullptr, 0, NN - NSPLIT);

    // s0: fused gather + epilogue, layer 0 -> HCAT cols 0-127
    gather_epi<<<GW, 256>>>(P0, P0 + 128, PE, rp, ps, bn0, bl0, HCAT);
    cudaEventRecord(evH0, 0);

    // s1: G4a: out = h1 @ Wo_top + bo  (overlaps G3)
    cudaStreamWaitEvent(s1, evH0, 0);
    gemm_mma<1><<<GT, 512, SM_SZ(1), s1>>>(HCAT, 256, BI + 6 * 65536, out, 128, bo, 0, NN);
    cudaEventRecord(evG4a, s1);

    // s0: G3: h1 @ [Wn1u | Wl1] -> P1
    gemm_mma<2><<<GT, 512, SM_SZ(2)>>>(HCAT, 256, BI + 4 * 65536, P1, 256, nullptr, 0, NN);

    // s0: fused gather + epilogue, layer 1 -> HCAT cols 128-255
    gather_epi<<<GW, 256>>>(P1, P1 + 128, PE + 128, rp, ps, bn1, bl1, HCAT + 128);

    // s0: G4b: out += h2 @ Wo_bot   (join s1)
    cudaStreamWaitEvent(0, evG4a, 0);
    gemm_mma<1><<<GT, 512, SM_SZ(1)>>>(HCAT + 128, 256, BI + 7 * 65536, out, 128, nullptr, 1, NN);
}

// round 14
// speedup vs baseline: 1.5144x; 1.0339x over previous
#include <cuda_runtime.h>
#include <cuda_bf16.h>
#include <cstdint>

#define NN 50000
#define NE 800000
#define D  128
#define PERSIST_CTAS 152

static __device__ __forceinline__ float rrelu_f(float x) {
    const float SLOPE = (1.0f/8.0f + 1.0f/3.0f) * 0.5f;
    return x >= 0.0f ? x : x * SLOPE;
}

// ---------------- scratch layout (floats) ----------------
#define ND        (NN * D)                 // 6,400,000
#define OFF_EA    0                        // Eagg 50k x 128
#define OFF_PE    (ND)                     // 50k x 256: [E0 | E1]
#define OFF_P0    (3 * ND)                 // 50k x 256: [x@Wn0u | x@Wl0]
#define OFF_P1    (5 * ND)                 // 50k x 256: [h1@Wn1u | h1@Wl1]
#define OFF_HCAT  (7 * ND)                 // 50k x 256
#define OFF_INT   (9 * ND)
#define NI_HIST 0
#define NI_INCL 50176
#define NI_BLK  100352
#define NI_BOFF 100416
#define NI_RP   100480
#define NI_WP   150912
#define NI_PS   201088
#define NI_PE   1001088
#define NI_TOTAL 1801088
#define SCRATCH_N (OFF_INT + NI_TOTAL)

__device__ float g_scratch[SCRATCH_N];

// bf16 weight images: 8 chunks x 64KB ([n][k] bf16 hi then lo).
// 0:Wn0u 1:Wl0 2:Wn0e 3:Wn1e 4:Wn1u 5:Wl1 6:Wo_top 7:Wo_bot
__device__ __align__(16) unsigned char g_bimg[8 * 65536];

// ---------------- PTX helpers ----------------
__device__ __forceinline__ uint32_t smem_u32(const void* p) {
    uint32_t a;
    asm("{ .reg .u64 t; cvta.to.shared.u64 t, %1; cvt.u32.u64 %0, t; }" : "=r"(a) : "l"(p));
    return a;
}

__device__ __forceinline__ void ldsm_x4(uint32_t addr, uint32_t* r) {
    asm volatile("ldmatrix.sync.aligned.m8n8.x4.shared.b16 {%0,%1,%2,%3}, [%4];"
                 : "=r"(r[0]), "=r"(r[1]), "=r"(r[2]), "=r"(r[3]) : "r"(addr));
}

__device__ __forceinline__ void mma_bf16(float* c, const uint32_t* a,
                                         uint32_t b0, uint32_t b1) {
    asm volatile("mma.sync.aligned.m16n8k16.row.col.f32.bf16.bf16.f32 "
                 "{%0,%1,%2,%3}, {%4,%5,%6,%7}, {%8,%9}, {%0,%1,%2,%3};"
                 : "+f"(c[0]), "+f"(c[1]), "+f"(c[2]), "+f"(c[3])
                 : "r"(a[0]), "r"(a[1]), "r"(a[2]), "r"(a[3]), "r"(b0), "r"(b1));
}

// ---------------- CSR build ----------------
__global__ void zero_hist(int* hist) {
    int i = blockIdx.x * blockDim.x + threadIdx.x;
    if (i < NN) hist[i] = 0;
}

__global__ void hist_k(const int* __restrict__ dst, int* __restrict__ hist) {
    int i = blockIdx.x * blockDim.x + threadIdx.x;
    if (i < NE) atomicAdd(hist + __ldg(dst + i), 1);
}

__global__ void scanA(const int* __restrict__ hist, int* __restrict__ incl,
                      int* __restrict__ blk) {
    __shared__ int s[1024];
    int t = threadIdx.x;
    int i = blockIdx.x * 1024 + t;
    int v = (i < NN) ? hist[i] : 0;
    s[t] = v;
    __syncthreads();
#pragma unroll
    for (int off = 1; off < 1024; off <<= 1) {
        int add = (t >= off) ? s[t - off] : 0;
        __syncthreads();
        s[t] += add;
        __syncthreads();
    }
    incl[i] = s[t];
    if (t == 1023) blk[blockIdx.x] = s[t];
}

__global__ void scanB(const int* __restrict__ blk, int* __restrict__ boff) {
    __shared__ int s[64];
    int t = threadIdx.x;
    if (t < 49) s[t] = blk[t];
    __syncthreads();
    if (t == 0) {
        int run = 0;
        for (int b = 0; b < 49; b++) { int v = s[b]; s[b] = run; run += v; }
    }
    __syncthreads();
    if (t < 49) boff[t] = s[t];
}

__global__ void scanC(const int* __restrict__ incl, const int* __restrict__ boff,
                      const int* __restrict__ hist,
                      int* __restrict__ rp, int* __restrict__ wp) {
    int t = threadIdx.x;
    int i = blockIdx.x * 1024 + t;
    if (i < NN) {
        int inc = incl[i] + boff[blockIdx.x];
        rp[i + 1] = inc;
        wp[i] = inc - hist[i];
    }
    if (i == 0) rp[0] = 0;
}

__global__ void permute_k(const int* __restrict__ src, const int* __restrict__ dst,
                          int* __restrict__ wp,
                          int* __restrict__ ps, int* __restrict__ pe) {
    int i = blockIdx.x * blockDim.x + threadIdx.x;
    if (i >= NE) return;
    int d = __ldg(dst + i);
    int pos = atomicAdd(wp + d, 1);
    ps[pos] = __ldg(src + i);
    pe[pos] = i;
}

// ---------------- CSR gathers ----------------
__global__ void gather_e(const float* __restrict__ e,
                         const int* __restrict__ rp,
                         const int* __restrict__ pe,
                         float* __restrict__ EA) {
    int w    = (blockIdx.x * blockDim.x + threadIdx.x) >> 5;
    int lane = threadIdx.x & 31;
    if (w >= NN) return;
    int beg = __ldg(rp + w), end = __ldg(rp + w + 1);
    float4 acc = make_float4(0.f, 0.f, 0.f, 0.f);
    for (int j = beg; j < end; j += 32) {
        int m = min(32, end - j);
        int eid = (lane < m) ? __ldg(pe + j + lane) : 0;
        for (int t = 0; t < m; t++) {
            int et = __shfl_sync(0xffffffffu, eid, t);
            float4 v = *reinterpret_cast<const float4*>(e + (size_t)et * D + lane * 4);
            acc.x += v.x; acc.y += v.y; acc.z += v.z; acc.w += v.w;
        }
    }
    *reinterpret_cast<float4*>(EA + (size_t)w * D + lane * 4) = acc;
}

// ---------------- fused gather + layer epilogue ----------------
// h = rrelu( (sum T[src] + EW[n])/max(cnt,1) + (cnt>0)*bn + Tb[n] + bl )
__global__ void gather_epi(const float* __restrict__ T,    // ld 256, cols 0-127
                           const float* __restrict__ Tb,   // ld 256
                           const float* __restrict__ EW,   // ld 256
                           const int* __restrict__ rp,
                           const int* __restrict__ ps,
                           const float* __restrict__ bn,
                           const float* __restrict__ bl,
                           float* __restrict__ hc) {       // ld 256
    int w    = (blockIdx.x * blockDim.x + threadIdx.x) >> 5;
    int lane = threadIdx.x & 31;
    if (w >= NN) return;
    int beg = __ldg(rp + w), end = __ldg(rp + w + 1);
    float4 acc = make_float4(0.f, 0.f, 0.f, 0.f);
    for (int j = beg; j < end; j += 32) {
        int m = min(32, end - j);
        int sidx = (lane < m) ? __ldg(ps + j + lane) : 0;
        for (int t = 0; t < m; t++) {
            int s = __shfl_sync(0xffffffffu, sidx, t);
            float4 v = *reinterpret_cast<const float4*>(T + (size_t)s * 256 + lane * 4);
            acc.x += v.x; acc.y += v.y; acc.z += v.z; acc.w += v.w;
        }
    }
    int cn = end - beg;
    float inv = 1.0f / fmaxf((float)cn, 1.0f);
    float g = (cn > 0) ? 1.0f : 0.0f;
    float4 ew = *reinterpret_cast<const float4*>(EW + (size_t)w * 256 + lane * 4);
    float4 tb = *reinterpret_cast<const float4*>(Tb + (size_t)w * 256 + lane * 4);
    float4 b4 = *reinterpret_cast<const float4*>(bn + lane * 4);
    float4 l4 = *reinterpret_cast<const float4*>(bl + lane * 4);
    float4 o;
    o.x = rrelu_f((acc.x + ew.x) * inv + g * b4.x + tb.x + l4.x);
    o.y = rrelu_f((acc.y + ew.y) * inv + g * b4.y + tb.y + l4.y);
    o.z = rrelu_f((acc.z + ew.z) * inv + g * b4.z + tb.z + l4.z);
    o.w = rrelu_f((acc.w + ew.w) * inv + g * b4.w + tb.w + l4.w);
    *reinterpret_cast<float4*>(hc + (size_t)w * 256 + lane * 4) = o;
}

// ---------------- weight image prep ----------------
__global__ void prep_B(const float* __restrict__ Wn0, const float* __restrict__ Wl0,
                       const float* __restrict__ Wn1, const float* __restrict__ Wl1,
                       const float* __restrict__ Wo, unsigned char* __restrict__ img) {
    int ci = blockIdx.x;
    const float* W;
    switch (ci) {
        case 0: W = Wn0; break;               // Wn0u
        case 1: W = Wl0; break;
        case 2: W = Wn0 + 128 * 128; break;   // Wn0e
        case 3: W = Wn1 + 128 * 128; break;   // Wn1e
        case 4: W = Wn1; break;               // Wn1u
        case 5: W = Wl1; break;
        case 6: W = Wo; break;
        default: W = Wo + 128 * 128; break;
    }
    unsigned char* hi_img = img + ci * 65536;
    unsigned char* lo_img = hi_img + 32768;

    __shared__ float sw[64][129];
    int t = threadIdx.x;  // 128
    for (int kt = 0; kt < 2; kt++) {
        for (int i = t; i < 64 * 128; i += 128)
            sw[i >> 7][i & 127] = W[kt * 64 * 128 + i];
        __syncthreads();
        int n = t;
#pragma unroll
        for (int u = 0; u < 8; u++) {
            union { __nv_bfloat16 h[8]; uint4 v; } hi;
            union { __nv_bfloat16 h[8]; uint4 v; } lo;
#pragma unroll
            for (int j = 0; j < 8; j++) {
                float f = sw[u * 8 + j][n];
                __nv_bfloat16 hb = __float2bfloat16(f);
                hi.h[j] = hb;
                lo.h[j] = __float2bfloat16(f - __bfloat162float(hb));
            }
            uint32_t off = (uint32_t)(n * 256 + kt * 128 + u * 16);
            *reinterpret_cast<uint4*>(hi_img + off) = hi.v;
            *reinterpret_cast<uint4*>(lo_img + off) = lo.v;
        }
        __syncthreads();
    }
}

// ---------------- HMMA bf16x3 GEMM: persistent CTAs, B resident ----------------
// 128 x (128*NCH) tile, K=128, 512 thr; CTA loops over m-tiles with B in smem.
#define SA_HI 0
#define SA_LO 34816
#define SB_BASE 69632
#define CHUNK_SM 69632
#define SM_SZ(NCH) (SB_BASE + (NCH) * CHUNK_SM)

template<int NCH>
__global__ __launch_bounds__(512, 1)
void gemm_mma(const float* __restrict__ A, int lda,
              const unsigned char* __restrict__ Bimg,
              float* __restrict__ C, int ldc,
              const float* __restrict__ bias, int accumulate, int M) {
    constexpr int MI = 2 * NCH;
    constexpr int NW = 4 * NCH;
    extern __shared__ unsigned char smem[];
    uint32_t sb = smem_u32(smem);
    int tid  = threadIdx.x;
    int lane = tid & 31;
    int wid  = tid >> 5;
    int wn   = wid % NW;
    int wm   = wid / NW;

    // ---- B: NCH chunk images -> smem once per CTA (re-strided 256 -> 272) ----
#pragma unroll
    for (int c = 0; c < NCH; c++) {
        const unsigned char* ch = Bimg + (size_t)c * 65536;
        unsigned char* db = smem + SB_BASE + c * CHUNK_SM;
#pragma unroll
        for (int i = 0; i < 4; i++) {
            int linear = tid + i * 512;
            int row = linear >> 4;
            int c16 = linear & 15;
            uint32_t soff = (uint32_t)(row * 256 + c16 * 16);
            uint32_t doff = (uint32_t)(row * 272 + c16 * 16);
            *reinterpret_cast<uint4*>(db + doff) =
                *reinterpret_cast<const uint4*>(ch + soff);
            *reinterpret_cast<uint4*>(db + 34816 + doff) =
                *reinterpret_cast<const uint4*>(ch + 32768 + soff);
        }
    }

    const int MT = (M + 127) >> 7;
    for (int tile = blockIdx.x; tile < MT; tile += gridDim.x) {
        int bm = tile << 7;
        __syncthreads();   // prior MMA done before A overwrite; also covers B on iter 0

        // ---- A: global f32 -> smem bf16 hi/lo ----
        {
            int r = tid >> 2;
            int q = tid & 3;
            bool valid = (bm + r) < M;
            const float4* ap = reinterpret_cast<const float4*>(
                A + (size_t)(bm + r) * lda + q * 32);
            float4 z4 = make_float4(0.f, 0.f, 0.f, 0.f);
#pragma unroll
            for (int u = 0; u < 4; u++) {
                float4 f0 = valid ? ap[u * 2]     : z4;
                float4 f1 = valid ? ap[u * 2 + 1] : z4;
                float fs[8] = {f0.x, f0.y, f0.z, f0.w, f1.x, f1.y, f1.z, f1.w};
                union { __nv_bfloat16 b[8]; uint4 v; } hi;
                union { __nv_bfloat16 b[8]; uint4 v; } lo;
#pragma unroll
                for (int j = 0; j < 8; j++) {
                    __nv_bfloat16 hb = __float2bfloat16(fs[j]);
                    hi.b[j] = hb;
                    lo.b[j] = __float2bfloat16(fs[j] - __bfloat162float(hb));
                }
                uint32_t off = (uint32_t)(r * 272 + q * 64 + u * 16);
                *reinterpret_cast<uint4*>(smem + SA_HI + off) = hi.v;
                *reinterpret_cast<uint4*>(smem + SA_LO + off) = lo.v;
            }
        }
        __syncthreads();

        float acc[MI][4][4];
#pragma unroll
        for (int mi = 0; mi < MI; mi++)
#pragma unroll
            for (int ni = 0; ni < 4; ni++)
#pragma unroll
                for (int q = 0; q < 4; q++) acc[mi][ni][q] = 0.f;

        uint32_t a_row = (uint32_t)(wm * (32 * NCH) + (lane & 15));
        uint32_t a_cb  = (uint32_t)((lane >> 4) * 16);
        uint32_t sbB   = sb + SB_BASE + (wn >> 2) * CHUNK_SM;
        uint32_t b_n   = (uint32_t)((wn & 3) * 32 + ((lane >> 4) << 3) + (lane & 7));
        uint32_t b_cb  = (uint32_t)(((lane >> 3) & 1) * 16);
#pragma unroll
        for (int ks = 0; ks < 8; ks++) {
            uint32_t kb = (uint32_t)(ks * 32);
            uint32_t Ahi[MI][4], Alo[MI][4];
#pragma unroll
            for (int mi = 0; mi < MI; mi++) {
                ldsm_x4(sb + SA_HI + (a_row + mi * 16) * 272 + kb + a_cb, Ahi[mi]);
                ldsm_x4(sb + SA_LO + (a_row + mi * 16) * 272 + kb + a_cb, Alo[mi]);
            }
#pragma unroll
            for (int nj = 0; nj < 2; nj++) {
                uint32_t bh[4], bl[4];
                uint32_t baddr = (b_n + nj * 16) * 272 + kb + b_cb;
                ldsm_x4(sbB + baddr, bh);
                ldsm_x4(sbB + 34816 + baddr, bl);
#pragma unroll
                for (int mi = 0; mi < MI; mi++) {
                    mma_bf16(acc[mi][2 * nj],     Ahi[mi], bh[0], bh[1]);
                    mma_bf16(acc[mi][2 * nj],     Ahi[mi], bl[0], bl[1]);
                    mma_bf16(acc[mi][2 * nj],     Alo[mi], bh[0], bh[1]);
                    mma_bf16(acc[mi][2 * nj + 1], Ahi[mi], bh[2], bh[3]);
                    mma_bf16(acc[mi][2 * nj + 1], Ahi[mi], bl[2], bl[3]);
                    mma_bf16(acc[mi][2 * nj + 1], Alo[mi], bh[2], bh[3]);
                }
            }
        }

        // ---- epilogue ----
        int lrow = lane >> 2;
        int lcol = (lane & 3) * 2;
#pragma unroll
        for (int mi = 0; mi < MI; mi++) {
            int row0 = bm + wm * (32 * NCH) + mi * 16 + lrow;
#pragma unroll
            for (int ni = 0; ni < 4; ni++) {
                int gcol = wn * 32 + ni * 8 + lcol;
                float b0 = 0.f, b1 = 0.f;
                if (bias) {
                    b0 = __ldg(bias + gcol);
                    b1 = __ldg(bias + gcol + 1);
                }
                if (row0 < M) {
                    float* cp = C + (size_t)row0 * ldc + gcol;
                    float2 v = make_float2(acc[mi][ni][0] + b0, acc[mi][ni][1] + b1);
                    if (accumulate) { float2 o = *reinterpret_cast<float2*>(cp); v.x += o.x; v.y += o.y; }
                    *reinterpret_cast<float2*>(cp) = v;
                }
                if (row0 + 8 < M) {
                    float* cp = C + (size_t)(row0 + 8) * ldc + gcol;
                    float2 v = make_float2(acc[mi][ni][2] + b0, acc[mi][ni][3] + b1);
                    if (accumulate) { float2 o = *reinterpret_cast<float2*>(cp); v.x += o.x; v.y += o.y; }
                    *reinterpret_cast<float2*>(cp) = v;
                }
            }
        }
    }
}

// ---------------- launch ----------------
extern "C" void kernel_launch(void* const* d_in, const int* in_sizes, int n_in,
                              void* d_out, int out_size) {
    const float* x   = (const float*)d_in[0];
    const float* e   = (const float*)d_in[1];
    const int*   src = (const int*)d_in[2];
    const int*   dst = (const int*)d_in[3];
    const float* Wn0 = (const float*)d_in[4];
    const float* bn0 = (const float*)d_in[5];
    const float* Wl0 = (const float*)d_in[6];
    const float* bl0 = (const float*)d_in[7];
    const float* Wn1 = (const float*)d_in[8];
    const float* bn1 = (const float*)d_in[9];
    const float* Wl1 = (const float*)d_in[10];
    const float* bl1 = (const float*)d_in[11];
    const float* Wo  = (const float*)d_in[12];
    const float* bo  = (const float*)d_in[13];
    float* out = (float*)d_out;

    float* S = nullptr;
    cudaGetSymbolAddress((void**)&S, g_scratch);
    unsigned char* BI = nullptr;
    cudaGetSymbolAddress((void**)&BI, g_bimg);

    float* EA   = S + OFF_EA;
    float* PE   = S + OFF_PE;
    float* P0   = S + OFF_P0;
    float* P1   = S + OFF_P1;
    float* HCAT = S + OFF_HCAT;
    int*   I    = (int*)(S + OFF_INT);
    int* hist = I + NI_HIST;
    int* incl = I + NI_INCL;
    int* blk  = I + NI_BLK;
    int* boff = I + NI_BOFF;
    int* rp   = I + NI_RP;
    int* wp   = I + NI_WP;
    int* ps   = I + NI_PS;
    int* pe   = I + NI_PE;

    static cudaStream_t s1 = nullptr;
    static cudaEvent_t evRoot, evE, evH0, evG4a;
    if (!s1) {
        cudaStreamCreateWithFlags(&s1, cudaStreamNonBlocking);
        cudaEventCreateWithFlags(&evRoot, cudaEventDisableTiming);
        cudaEventCreateWithFlags(&evE,    cudaEventDisableTiming);
        cudaEventCreateWithFlags(&evH0,   cudaEventDisableTiming);
        cudaEventCreateWithFlags(&evG4a,  cudaEventDisableTiming);
    }

    cudaFuncSetAttribute(gemm_mma<2>,
                         cudaFuncAttributeMaxDynamicSharedMemorySize, SM_SZ(2));
    cudaFuncSetAttribute(gemm_mma<1>,
                         cudaFuncAttributeMaxDynamicSharedMemorySize, SM_SZ(1));

    const int GW = (NN * 32 + 255) / 256;     // warp-per-node grids
    const dim3 GP(PERSIST_CTAS);

    // fork root
    cudaEventRecord(evRoot, 0);
    cudaStreamWaitEvent(s1, evRoot, 0);

    // s1: CSR build + edge-feature gather
    zero_hist<<<(NN + 255) / 256, 256, 0, s1>>>(hist);
    hist_k<<<(NE + 255) / 256, 256, 0, s1>>>(dst, hist);
    scanA<<<49, 1024, 0, s1>>>(hist, incl, blk);
    scanB<<<1, 64, 0, s1>>>(blk, boff);
    scanC<<<49, 1024, 0, s1>>>(incl, boff, hist, rp, wp);
    permute_k<<<(NE + 255) / 256, 256, 0, s1>>>(src, dst, wp, ps, pe);
    gather_e<<<GW, 256, 0, s1>>>(e, rp, pe, EA);
    cudaEventRecord(evE, s1);

    // s0: weight images, G1: x @ [Wn0u | Wl0] -> P0
    prep_B<<<8, 128>>>(Wn0, Wl0, Wn1, Wl1, Wo, BI);
    gemm_mma<2><<<GP, 512, SM_SZ(2)>>>(x, D, BI + 0 * 65536, P0, 256, nullptr, 0, NN);

    // s0: G2: EA @ [Wn0e | Wn1e] -> PE   (needs EA)
    cudaStreamWaitEvent(0, evE, 0);
    gemm_mma<2><<<GP, 512, SM_SZ(2)>>>(EA, D, BI + 2 * 65536, PE, 256, nullptr, 0, NN);

    // s0: fused gather + epilogue, layer 0 -> HCAT cols 0-127
    gather_epi<<<GW, 256>>>(P0, P0 + 128, PE, rp, ps, bn0, bl0, HCAT);
    cudaEventRecord(evH0, 0);

    // s1: G4a: out = h1 @ Wo_top + bo  (overlaps G3)
    cudaStreamWaitEvent(s1, evH0, 0);
    gemm_mma<1><<<GP, 512, SM_SZ(1), s1>>>(HCAT, 256, BI + 6 * 65536, out, 128, bo, 0, NN);
    cudaEventRecord(evG4a, s1);

    // s0: G3: h1 @ [Wn1u | Wl1] -> P1
    gemm_mma<2><<<GP, 512, SM_SZ(2)>>>(HCAT, 256, BI + 4 * 65536, P1, 256, nullptr, 0, NN);

    // s0: fused gather + epilogue, layer 1 -> HCAT cols 128-255
    gather_epi<<<GW, 256>>>(P1, P1 + 128, PE + 128, rp, ps, bn1, bl1, HCAT + 128);

    // s0: G4b: out += h2 @ Wo_bot   (join s1)
    cudaStreamWaitEvent(0, evG4a, 0);
    gemm_mma<1><<<GP, 512, SM_SZ(1)>>>(HCAT + 128, 256, BI + 7 * 65536, out, 128, nullptr, 1, NN);
}

// round 15
// speedup vs baseline: 1.5590x; 1.0295x over previous
#include <cuda_runtime.h>
#include <cuda_bf16.h>
#include <cstdint>

#define NN 50000
#define NE 800000
#define D  128
#define PERSIST_CTAS 152

static __device__ __forceinline__ float rrelu_f(float x) {
    const float SLOPE = (1.0f/8.0f + 1.0f/3.0f) * 0.5f;
    return x >= 0.0f ? x : x * SLOPE;
}

// ---------------- scratch layout (floats) ----------------
#define ND        (NN * D)                 // 6,400,000
#define OFF_EA    0                        // Eagg 50k x 128
#define OFF_PE    (ND)                     // 50k x 256: [E0 | E1]
#define OFF_P0    (3 * ND)                 // 50k x 256: [x@Wn0u | x@Wl0]
#define OFF_P1    (5 * ND)                 // 50k x 256: [h1@Wn1u | h1@Wl1]
#define OFF_HCAT  (7 * ND)                 // 50k x 256
#define OFF_INT   (9 * ND)
#define NI_HIST 0
#define NI_INCL 50176
#define NI_BLK  100352
#define NI_BOFF 100416
#define NI_RP   100480
#define NI_WP   150912
#define NI_PS   201088
#define NI_PE   1001088
#define NI_TOTAL 1801088
#define SCRATCH_N (OFF_INT + NI_TOTAL)

__device__ float g_scratch[SCRATCH_N];

// bf16 weight images: 8 chunks x 64KB ([n][k] bf16 hi then lo).
// 0:Wn0u 1:Wl0 2:Wn0e 3:Wn1e 4:Wn1u 5:Wl1 6:Wo_top 7:Wo_bot
__device__ __align__(16) unsigned char g_bimg[8 * 65536];

// ---------------- PTX helpers ----------------
__device__ __forceinline__ uint32_t smem_u32(const void* p) {
    uint32_t a;
    asm("{ .reg .u64 t; cvta.to.shared.u64 t, %1; cvt.u32.u64 %0, t; }" : "=r"(a) : "l"(p));
    return a;
}

__device__ __forceinline__ void ldsm_x4(uint32_t addr, uint32_t* r) {
    asm volatile("ldmatrix.sync.aligned.m8n8.x4.shared.b16 {%0,%1,%2,%3}, [%4];"
                 : "=r"(r[0]), "=r"(r[1]), "=r"(r[2]), "=r"(r[3]) : "r"(addr));
}

__device__ __forceinline__ void mma_bf16(float* c, const uint32_t* a,
                                         uint32_t b0, uint32_t b1) {
    asm volatile("mma.sync.aligned.m16n8k16.row.col.f32.bf16.bf16.f32 "
                 "{%0,%1,%2,%3}, {%4,%5,%6,%7}, {%8,%9}, {%0,%1,%2,%3};"
                 : "+f"(c[0]), "+f"(c[1]), "+f"(c[2]), "+f"(c[3])
                 : "r"(a[0]), "r"(a[1]), "r"(a[2]), "r"(a[3]), "r"(b0), "r"(b1));
}

__device__ __forceinline__ void bar_sync(int id, int cnt) {
    asm volatile("bar.sync %0, %1;" :: "r"(id), "r"(cnt) : "memory");
}

// ---------------- CSR build ----------------
__global__ void zero_hist(int* hist) {
    int i = blockIdx.x * blockDim.x + threadIdx.x;
    if (i < NN) hist[i] = 0;
}

__global__ void hist_k(const int* __restrict__ dst, int* __restrict__ hist) {
    int i = blockIdx.x * blockDim.x + threadIdx.x;
    if (i < NE) atomicAdd(hist + __ldg(dst + i), 1);
}

__global__ void scanA(const int* __restrict__ hist, int* __restrict__ incl,
                      int* __restrict__ blk) {
    __shared__ int s[1024];
    int t = threadIdx.x;
    int i = blockIdx.x * 1024 + t;
    int v = (i < NN) ? hist[i] : 0;
    s[t] = v;
    __syncthreads();
#pragma unroll
    for (int off = 1; off < 1024; off <<= 1) {
        int add = (t >= off) ? s[t - off] : 0;
        __syncthreads();
        s[t] += add;
        __syncthreads();
    }
    incl[i] = s[t];
    if (t == 1023) blk[blockIdx.x] = s[t];
}

__global__ void scanB(const int* __restrict__ blk, int* __restrict__ boff) {
    __shared__ int s[64];
    int t = threadIdx.x;
    if (t < 49) s[t] = blk[t];
    __syncthreads();
    if (t == 0) {
        int run = 0;
        for (int b = 0; b < 49; b++) { int v = s[b]; s[b] = run; run += v; }
    }
    __syncthreads();
    if (t < 49) boff[t] = s[t];
}

__global__ void scanC(const int* __restrict__ incl, const int* __restrict__ boff,
                      const int* __restrict__ hist,
                      int* __restrict__ rp, int* __restrict__ wp) {
    int t = threadIdx.x;
    int i = blockIdx.x * 1024 + t;
    if (i < NN) {
        int inc = incl[i] + boff[blockIdx.x];
        rp[i + 1] = inc;
        wp[i] = inc - hist[i];
    }
    if (i == 0) rp[0] = 0;
}

__global__ void permute_k(const int* __restrict__ src, const int* __restrict__ dst,
                          int* __restrict__ wp,
                          int* __restrict__ ps, int* __restrict__ pe) {
    int i = blockIdx.x * blockDim.x + threadIdx.x;
    if (i >= NE) return;
    int d = __ldg(dst + i);
    int pos = atomicAdd(wp + d, 1);
    ps[pos] = __ldg(src + i);
    pe[pos] = i;
}

// ---------------- CSR gathers ----------------
__global__ void gather_e(const float* __restrict__ e,
                         const int* __restrict__ rp,
                         const int* __restrict__ pe,
                         float* __restrict__ EA) {
    int w    = (blockIdx.x * blockDim.x + threadIdx.x) >> 5;
    int lane = threadIdx.x & 31;
    if (w >= NN) return;
    int beg = __ldg(rp + w), end = __ldg(rp + w + 1);
    float4 acc = make_float4(0.f, 0.f, 0.f, 0.f);
    for (int j = beg; j < end; j += 32) {
        int m = min(32, end - j);
        int eid = (lane < m) ? __ldg(pe + j + lane) : 0;
        for (int t = 0; t < m; t++) {
            int et = __shfl_sync(0xffffffffu, eid, t);
            float4 v = *reinterpret_cast<const float4*>(e + (size_t)et * D + lane * 4);
            acc.x += v.x; acc.y += v.y; acc.z += v.z; acc.w += v.w;
        }
    }
    *reinterpret_cast<float4*>(EA + (size_t)w * D + lane * 4) = acc;
}

// ---------------- fused gather + layer epilogue ----------------
// h = rrelu( (sum T[src] + EW[n])/max(cnt,1) + (cnt>0)*bn + Tb[n] + bl )
__global__ void gather_epi(const float* __restrict__ T,    // ld 256, cols 0-127
                           const float* __restrict__ Tb,   // ld 256
                           const float* __restrict__ EW,   // ld 256
                           const int* __restrict__ rp,
                           const int* __restrict__ ps,
                           const float* __restrict__ bn,
                           const float* __restrict__ bl,
                           float* __restrict__ hc) {       // ld 256
    int w    = (blockIdx.x * blockDim.x + threadIdx.x) >> 5;
    int lane = threadIdx.x & 31;
    if (w >= NN) return;
    int beg = __ldg(rp + w), end = __ldg(rp + w + 1);
    float4 acc = make_float4(0.f, 0.f, 0.f, 0.f);
    for (int j = beg; j < end; j += 32) {
        int m = min(32, end - j);
        int sidx = (lane < m) ? __ldg(ps + j + lane) : 0;
        for (int t = 0; t < m; t++) {
            int s = __shfl_sync(0xffffffffu, sidx, t);
            float4 v = *reinterpret_cast<const float4*>(T + (size_t)s * 256 + lane * 4);
            acc.x += v.x; acc.y += v.y; acc.z += v.z; acc.w += v.w;
        }
    }
    int cn = end - beg;
    float inv = 1.0f / fmaxf((float)cn, 1.0f);
    float g = (cn > 0) ? 1.0f : 0.0f;
    float4 ew = *reinterpret_cast<const float4*>(EW + (size_t)w * 256 + lane * 4);
    float4 tb = *reinterpret_cast<const float4*>(Tb + (size_t)w * 256 + lane * 4);
    float4 b4 = *reinterpret_cast<const float4*>(bn + lane * 4);
    float4 l4 = *reinterpret_cast<const float4*>(bl + lane * 4);
    float4 o;
    o.x = rrelu_f((acc.x + ew.x) * inv + g * b4.x + tb.x + l4.x);
    o.y = rrelu_f((acc.y + ew.y) * inv + g * b4.y + tb.y + l4.y);
    o.z = rrelu_f((acc.z + ew.z) * inv + g * b4.z + tb.z + l4.z);
    o.w = rrelu_f((acc.w + ew.w) * inv + g * b4.w + tb.w + l4.w);
    *reinterpret_cast<float4*>(hc + (size_t)w * 256 + lane * 4) = o;
}

// ---------------- weight image prep ----------------
__global__ void prep_B(const float* __restrict__ Wn0, const float* __restrict__ Wl0,
                       const float* __restrict__ Wn1, const float* __restrict__ Wl1,
                       const float* __restrict__ Wo, unsigned char* __restrict__ img) {
    int ci = blockIdx.x;
    const float* W;
    switch (ci) {
        case 0: W = Wn0; break;               // Wn0u
        case 1: W = Wl0; break;
        case 2: W = Wn0 + 128 * 128; break;   // Wn0e
        case 3: W = Wn1 + 128 * 128; break;   // Wn1e
        case 4: W = Wn1; break;               // Wn1u
        case 5: W = Wl1; break;
        case 6: W = Wo; break;
        default: W = Wo + 128 * 128; break;
    }
    unsigned char* hi_img = img + ci * 65536;
    unsigned char* lo_img = hi_img + 32768;

    __shared__ float sw[64][129];
    int t = threadIdx.x;  // 128
    for (int kt = 0; kt < 2; kt++) {
        for (int i = t; i < 64 * 128; i += 128)
            sw[i >> 7][i & 127] = W[kt * 64 * 128 + i];
        __syncthreads();
        int n = t;
#pragma unroll
        for (int u = 0; u < 8; u++) {
            union { __nv_bfloat16 h[8]; uint4 v; } hi;
            union { __nv_bfloat16 h[8]; uint4 v; } lo;
#pragma unroll
            for (int j = 0; j < 8; j++) {
                float f = sw[u * 8 + j][n];
                __nv_bfloat16 hb = __float2bfloat16(f);
                hi.h[j] = hb;
                lo.h[j] = __float2bfloat16(f - __bfloat162float(hb));
            }
            uint32_t off = (uint32_t)(n * 256 + kt * 128 + u * 16);
            *reinterpret_cast<uint4*>(hi_img + off) = hi.v;
            *reinterpret_cast<uint4*>(lo_img + off) = lo.v;
        }
        __syncthreads();
    }
}

// ---------------- HMMA bf16x3 GEMM: persistent CTAs, split-barrier pipeline ----
// 128 x (128*NCH) tile, K=128, 512 thr; CTA loops over m-tiles with B resident.
// Warps in wm-group g only read A rows of group g; per-group named barriers let
// one group's MMA overlap the other group's A-load latency.
#define SA_HI 0
#define SA_LO 34816
#define SB_BASE 69632
#define CHUNK_SM 69632
#define SM_SZ(NCH) (SB_BASE + (NCH) * CHUNK_SM)

template<int NCH>
__global__ __launch_bounds__(512, 1)
void gemm_mma(const float* __restrict__ A, int lda,
              const unsigned char* __restrict__ Bimg,
              float* __restrict__ C, int ldc,
              const float* __restrict__ bias, int accumulate, int M) {
    constexpr int MI = 2 * NCH;
    constexpr int NW = 4 * NCH;
    constexpr int NGROUPS = 16 / NW;          // 2 (NCH=2) or 4 (NCH=1)
    constexpr int GT = 512 / NGROUPS;         // 256 or 128 threads/group
    extern __shared__ unsigned char smem[];
    uint32_t sb = smem_u32(smem);
    int tid  = threadIdx.x;
    int lane = tid & 31;
    int wid  = tid >> 5;
    int wn   = wid % NW;
    int wm   = wid / NW;
    int grp  = tid / GT;                       // == wm
    int barid = 1 + grp;

    // ---- B: NCH chunk images -> smem once per CTA (re-strided 256 -> 272) ----
#pragma unroll
    for (int c = 0; c < NCH; c++) {
        const unsigned char* ch = Bimg + (size_t)c * 65536;
        unsigned char* db = smem + SB_BASE + c * CHUNK_SM;
#pragma unroll
        for (int i = 0; i < 4; i++) {
            int linear = tid + i * 512;
            int row = linear >> 4;
            int c16 = linear & 15;
            uint32_t soff = (uint32_t)(row * 256 + c16 * 16);
            uint32_t doff = (uint32_t)(row * 272 + c16 * 16);
            *reinterpret_cast<uint4*>(db + doff) =
                *reinterpret_cast<const uint4*>(ch + soff);
            *reinterpret_cast<uint4*>(db + 34816 + doff) =
                *reinterpret_cast<const uint4*>(ch + 32768 + soff);
        }
    }
    __syncthreads();   // B visible to all groups

    const int MT = (M + 127) >> 7;
    for (int tile = blockIdx.x; tile < MT; tile += gridDim.x) {
        int bm = tile << 7;

        // ---- A: global f32 -> smem bf16 hi/lo (own group's rows only) ----
        {
            int r = tid >> 2;          // rows [grp*128/NGROUPS, ...): matches wm slice
            int q = tid & 3;
            bool valid = (bm + r) < M;
            const float4* ap = reinterpret_cast<const float4*>(
                A + (size_t)(bm + r) * lda + q * 32);
            float4 z4 = make_float4(0.f, 0.f, 0.f, 0.f);
#pragma unroll
            for (int u = 0; u < 4; u++) {
                float4 f0 = valid ? ap[u * 2]     : z4;
                float4 f1 = valid ? ap[u * 2 + 1] : z4;
                float fs[8] = {f0.x, f0.y, f0.z, f0.w, f1.x, f1.y, f1.z, f1.w};
                union { __nv_bfloat16 b[8]; uint4 v; } hi;
                union { __nv_bfloat16 b[8]; uint4 v; } lo;
#pragma unroll
                for (int j = 0; j < 8; j++) {
                    __nv_bfloat16 hb = __float2bfloat16(fs[j]);
                    hi.b[j] = hb;
                    lo.b[j] = __float2bfloat16(fs[j] - __bfloat162float(hb));
                }
                uint32_t off = (uint32_t)(r * 272 + q * 64 + u * 16);
                *reinterpret_cast<uint4*>(smem + SA_HI + off) = hi.v;
                *reinterpret_cast<uint4*>(smem + SA_LO + off) = lo.v;
            }
        }
        bar_sync(barid, GT);           // own group's A staged

        float acc[MI][4][4];
#pragma unroll
        for (int mi = 0; mi < MI; mi++)
#pragma unroll
            for (int ni = 0; ni < 4; ni++)
#pragma unroll
                for (int q = 0; q < 4; q++) acc[mi][ni][q] = 0.f;

        uint32_t a_row = (uint32_t)(wm * (32 * NCH) + (lane & 15));
        uint32_t a_cb  = (uint32_t)((lane >> 4) * 16);
        uint32_t sbB   = sb + SB_BASE + (wn >> 2) * CHUNK_SM;
        uint32_t b_n   = (uint32_t)((wn & 3) * 32 + ((lane >> 4) << 3) + (lane & 7));
        uint32_t b_cb  = (uint32_t)(((lane >> 3) & 1) * 16);
#pragma unroll
        for (int ks = 0; ks < 8; ks++) {
            uint32_t kb = (uint32_t)(ks * 32);
            uint32_t Ahi[MI][4], Alo[MI][4];
#pragma unroll
            for (int mi = 0; mi < MI; mi++) {
                ldsm_x4(sb + SA_HI + (a_row + mi * 16) * 272 + kb + a_cb, Ahi[mi]);
                ldsm_x4(sb + SA_LO + (a_row + mi * 16) * 272 + kb + a_cb, Alo[mi]);
            }
#pragma unroll
            for (int nj = 0; nj < 2; nj++) {
                uint32_t bh[4], bl[4];
                uint32_t baddr = (b_n + nj * 16) * 272 + kb + b_cb;
                ldsm_x4(sbB + baddr, bh);
                ldsm_x4(sbB + 34816 + baddr, bl);
#pragma unroll
                for (int mi = 0; mi < MI; mi++) {
                    mma_bf16(acc[mi][2 * nj],     Ahi[mi], bh[0], bh[1]);
                    mma_bf16(acc[mi][2 * nj],     Ahi[mi], bl[0], bl[1]);
                    mma_bf16(acc[mi][2 * nj],     Alo[mi], bh[0], bh[1]);
                    mma_bf16(acc[mi][2 * nj + 1], Ahi[mi], bh[2], bh[3]);
                    mma_bf16(acc[mi][2 * nj + 1], Ahi[mi], bl[2], bl[3]);
                    mma_bf16(acc[mi][2 * nj + 1], Alo[mi], bh[2], bh[3]);
                }
            }
        }

        // ---- epilogue ----
        int lrow = lane >> 2;
        int lcol = (lane & 3) * 2;
#pragma unroll
        for (int mi = 0; mi < MI; mi++) {
            int row0 = bm + wm * (32 * NCH) + mi * 16 + lrow;
#pragma unroll
            for (int ni = 0; ni < 4; ni++) {
                int gcol = wn * 32 + ni * 8 + lcol;
                float b0 = 0.f, b1 = 0.f;
                if (bias) {
                    b0 = __ldg(bias + gcol);
                    b1 = __ldg(bias + gcol + 1);
                }
                if (row0 < M) {
                    float* cp = C + (size_t)row0 * ldc + gcol;
                    float2 v = make_float2(acc[mi][ni][0] + b0, acc[mi][ni][1] + b1);
                    if (accumulate) { float2 o = *reinterpret_cast<float2*>(cp); v.x += o.x; v.y += o.y; }
                    *reinterpret_cast<float2*>(cp) = v;
                }
                if (row0 + 8 < M) {
                    float* cp = C + (size_t)(row0 + 8) * ldc + gcol;
                    float2 v = make_float2(acc[mi][ni][2] + b0, acc[mi][ni][3] + b1);
                    if (accumulate) { float2 o = *reinterpret_cast<float2*>(cp); v.x += o.x; v.y += o.y; }
                    *reinterpret_cast<float2*>(cp) = v;
                }
            }
        }
        bar_sync(barid, GT);           // group's ldsm done before next A overwrite
    }
}

// ---------------- launch ----------------
extern "C" void kernel_launch(void* const* d_in, const int* in_sizes, int n_in,
                              void* d_out, int out_size) {
    const float* x   = (const float*)d_in[0];
    const float* e   = (const float*)d_in[1];
    const int*   src = (const int*)d_in[2];
    const int*   dst = (const int*)d_in[3];
    const float* Wn0 = (const float*)d_in[4];
    const float* bn0 = (const float*)d_in[5];
    const float* Wl0 = (const float*)d_in[6];
    const float* bl0 = (const float*)d_in[7];
    const float* Wn1 = (const float*)d_in[8];
    const float* bn1 = (const float*)d_in[9];
    const float* Wl1 = (const float*)d_in[10];
    const float* bl1 = (const float*)d_in[11];
    const float* Wo  = (const float*)d_in[12];
    const float* bo  = (const float*)d_in[13];
    float* out = (float*)d_out;

    float* S = nullptr;
    cudaGetSymbolAddress((void**)&S, g_scratch);
    unsigned char* BI = nullptr;
    cudaGetSymbolAddress((void**)&BI, g_bimg);

    float* EA   = S + OFF_EA;
    float* PE   = S + OFF_PE;
    float* P0   = S + OFF_P0;
    float* P1   = S + OFF_P1;
    float* HCAT = S + OFF_HCAT;
    int*   I    = (int*)(S + OFF_INT);
    int* hist = I + NI_HIST;
    int* incl = I + NI_INCL;
    int* blk  = I + NI_BLK;
    int* boff = I + NI_BOFF;
    int* rp   = I + NI_RP;
    int* wp   = I + NI_WP;
    int* ps   = I + NI_PS;
    int* pe   = I + NI_PE;

    static cudaStream_t s1 = nullptr;
    static cudaEvent_t evRoot, evE, evH0, evG4a;
    if (!s1) {
        cudaStreamCreateWithFlags(&s1, cudaStreamNonBlocking);
        cudaEventCreateWithFlags(&evRoot, cudaEventDisableTiming);
        cudaEventCreateWithFlags(&evE,    cudaEventDisableTiming);
        cudaEventCreateWithFlags(&evH0,   cudaEventDisableTiming);
        cudaEventCreateWithFlags(&evG4a,  cudaEventDisableTiming);
    }

    cudaFuncSetAttribute(gemm_mma<2>,
                         cudaFuncAttributeMaxDynamicSharedMemorySize, SM_SZ(2));
    cudaFuncSetAttribute(gemm_mma<1>,
                         cudaFuncAttributeMaxDynamicSharedMemorySize, SM_SZ(1));

    const int GW = (NN * 32 + 255) / 256;     // warp-per-node grids
    const dim3 GP(PERSIST_CTAS);

    // fork root
    cudaEventRecord(evRoot, 0);
    cudaStreamWaitEvent(s1, evRoot, 0);

    // s1: CSR build + edge-feature gather
    zero_hist<<<(NN + 255) / 256, 256, 0, s1>>>(hist);
    hist_k<<<(NE + 255) / 256, 256, 0, s1>>>(dst, hist);
    scanA<<<49, 1024, 0, s1>>>(hist, incl, blk);
    scanB<<<1, 64, 0, s1>>>(blk, boff);
    scanC<<<49, 1024, 0, s1>>>(incl, boff, hist, rp, wp);
    permute_k<<<(NE + 255) / 256, 256, 0, s1>>>(src, dst, wp, ps, pe);
    gather_e<<<GW, 256, 0, s1>>>(e, rp, pe, EA);
    cudaEventRecord(evE, s1);

    // s0: weight images, G1: x @ [Wn0u | Wl0] -> P0
    prep_B<<<8, 128>>>(Wn0, Wl0, Wn1, Wl1, Wo, BI);
    gemm_mma<2><<<GP, 512, SM_SZ(2)>>>(x, D, BI + 0 * 65536, P0, 256, nullptr, 0, NN);

    // s0: G2: EA @ [Wn0e | Wn1e] -> PE   (needs EA)
    cudaStreamWaitEvent(0, evE, 0);
    gemm_mma<2><<<GP, 512, SM_SZ(2)>>>(EA, D, BI + 2 * 65536, PE, 256, nullptr, 0, NN);

    // s0: fused gather + epilogue, layer 0 -> HCAT cols 0-127
    gather_epi<<<GW, 256>>>(P0, P0 + 128, PE, rp, ps, bn0, bl0, HCAT);
    cudaEventRecord(evH0, 0);

    // s1: G4a: out = h1 @ Wo_top + bo  (overlaps G3)
    cudaStreamWaitEvent(s1, evH0, 0);
    gemm_mma<1><<<GP, 512, SM_SZ(1), s1>>>(HCAT, 256, BI + 6 * 65536, out, 128, bo, 0, NN);
    cudaEventRecord(evG4a, s1);

    // s0: G3: h1 @ [Wn1u | Wl1] -> P1
    gemm_mma<2><<<GP, 512, SM_SZ(2)>>>(HCAT, 256, BI + 4 * 65536, P1, 256, nullptr, 0, NN);

    // s0: fused gather + epilogue, layer 1 -> HCAT cols 128-255
    gather_epi<<<GW, 256>>>(P1, P1 + 128, PE + 128, rp, ps, bn1, bl1, HCAT + 128);

    // s0: G4b: out += h2 @ Wo_bot   (join s1)
    cudaStreamWaitEvent(0, evG4a, 0);
    gemm_mma<1><<<GP, 512, SM_SZ(1)>>>(HCAT + 128, 256, BI + 7 * 65536, out, 128, nullptr, 1, NN);
}